// round 2
// baseline (speedup 1.0000x reference)
#include <cuda_runtime.h>
#include <cuda_bf16.h>

#define LSEQ 4608
#define CDIM 640
#define DI   1280
#define DXZ  2560
#define NPROJ 56
#define RANK  40
#define PLANE 2304          // 48*48
#define XFSZ  (640*2304)    // elements in xf output
#define PSLICE (LSEQ*NPROJ) // 258048

// ---------------- scratch (static device allocations; no cudaMalloc) ----------------
__device__ float g_xn  [LSEQ*CDIM];   // layernorm output
__device__ float g_xz  [LSEQ*DXZ];    // xn @ W_in  (xp | z)
__device__ float g_xa  [LSEQ*DI];     // silu(conv(xp))
__device__ float g_proj[LSEQ*NPROJ];  // xa @ W_xproj  (dtin | B | C)
__device__ float g_pp  [4*PSLICE];    // split-K partials for proj
__device__ float g_dt  [LSEQ*DI];     // softplus(proj[:, :40] @ W_dt + bias)
__device__ float g_yo  [LSEQ*DI];     // gated ssm output

// ---------------- helpers ----------------
__device__ __forceinline__ float silu_f(float v){
    return v / (1.0f + __expf(-v));
}

// ---------------- 1) gather + layernorm ----------------
__global__ void ln_kernel(const float* __restrict__ x, const float* __restrict__ yy,
                          const float* __restrict__ g, const float* __restrict__ b){
    int l  = blockIdx.x;
    int h  = l / 96;
    int w2 = l - h * 96;
    const float* src = (w2 < 48) ? (x + h*48 + w2) : (yy + h*48 + (w2-48));
    int t = threadIdx.x;   // 256 threads

    float v0 = src[(size_t)t       * PLANE];
    float v1 = src[(size_t)(t+256) * PLANE];
    float v2 = (t < 128) ? src[(size_t)(t+512) * PLANE] : 0.f;

    float s  = v0 + v1 + v2;
    float s2 = v0*v0 + v1*v1 + v2*v2;
    #pragma unroll
    for (int o = 16; o > 0; o >>= 1){
        s  += __shfl_xor_sync(0xffffffffu, s , o);
        s2 += __shfl_xor_sync(0xffffffffu, s2, o);
    }
    __shared__ float rs[8], rs2[8];
    int wid = t >> 5, lid = t & 31;
    if (lid == 0){ rs[wid] = s; rs2[wid] = s2; }
    __syncthreads();
    if (t == 0){
        float a = 0.f, a2 = 0.f;
        #pragma unroll
        for (int i = 0; i < 8; i++){ a += rs[i]; a2 += rs2[i]; }
        rs[0] = a; rs2[0] = a2;
    }
    __syncthreads();
    float mean = rs[0]  * (1.f/640.f);
    float var  = rs2[0] * (1.f/640.f) - mean*mean;
    float inv  = rsqrtf(var + 1e-5f);

    float* dst = g_xn + (size_t)l * CDIM;
    dst[t]       = (v0 - mean) * inv * g[t]       + b[t];
    dst[t + 256] = (v1 - mean) * inv * g[t + 256] + b[t + 256];
    if (t < 128)
        dst[t + 512] = (v2 - mean) * inv * g[t + 512] + b[t + 512];
}

// ---------------- 2/7) 128x128 double-buffered BK=16 SGEMM ----------------
// MODE 0: C[row*N + col] = acc                      (GEMM1: xn @ W_in -> xz)
// MODE 1: out scatter + residual                    (GEMM2: yo @ W_out + seq -> d_out)
template<int MODE>
__global__ void __launch_bounds__(256)
sgemm_db(const float* __restrict__ A, const float* __restrict__ B,
         float* __restrict__ C, int K, int N,
         const float* __restrict__ rx, const float* __restrict__ ry,
         float* __restrict__ outp){
    __shared__ float As[2][16][128];
    __shared__ float Bs[2][16][128];
    int tid = threadIdx.x;
    int bx = blockIdx.x, by = blockIdx.y;
    int wid  = tid >> 5, lane = tid & 31;
    int wr = wid >> 2, wc = wid & 3;       // warp grid 2 x 4  (64 x 32 warp tiles)
    int lr = lane >> 2, lc = lane & 3;     // lane grid 8 x 4  (8 x 8 thread tiles)
    int arow = wr*64 + lr*8;
    int bcol = wc*32 + lc*8;

    // global-load indices
    int la_row = tid >> 1;                 // 0..127
    int la_k   = (tid & 1) * 8;            // 0 or 8
    int lb_row = tid >> 4;                 // 0..15
    int lb_col = (tid & 15) * 8;

    const float* Ap = A + (size_t)(by*128 + la_row) * K + la_k;
    const float* Bp = B + (size_t)lb_row * N + bx*128 + lb_col;

    float4 a0g = *(const float4*)Ap;
    float4 a1g = *(const float4*)(Ap + 4);
    float4 b0g = *(const float4*)Bp;
    float4 b1g = *(const float4*)(Bp + 4);

    float acc[8][8];
    #pragma unroll
    for (int i = 0; i < 8; i++)
        #pragma unroll
        for (int j = 0; j < 8; j++) acc[i][j] = 0.f;

    // stage tile 0 into buffer 0
    As[0][la_k+0][la_row] = a0g.x;
    As[0][la_k+1][la_row] = a0g.y;
    As[0][la_k+2][la_row] = a0g.z;
    As[0][la_k+3][la_row] = a0g.w;
    As[0][la_k+4][la_row] = a1g.x;
    As[0][la_k+5][la_row] = a1g.y;
    As[0][la_k+6][la_row] = a1g.z;
    As[0][la_k+7][la_row] = a1g.w;
    *(float4*)(&Bs[0][lb_row][lb_col])     = b0g;
    *(float4*)(&Bs[0][lb_row][lb_col + 4]) = b1g;
    __syncthreads();

    int nt = K / 16;
    int cur = 0;
    for (int t = 0; t < nt; t++){
        if (t + 1 < nt){
            Ap += 16;
            Bp += (size_t)16 * N;
            a0g = *(const float4*)Ap;
            a1g = *(const float4*)(Ap + 4);
            b0g = *(const float4*)Bp;
            b1g = *(const float4*)(Bp + 4);
        }
        #pragma unroll
        for (int k = 0; k < 16; k++){
            float4 av0 = *(const float4*)(&As[cur][k][arow]);
            float4 av1 = *(const float4*)(&As[cur][k][arow + 4]);
            float4 bv0 = *(const float4*)(&Bs[cur][k][bcol]);
            float4 bv1 = *(const float4*)(&Bs[cur][k][bcol + 4]);
            float ar[8] = {av0.x,av0.y,av0.z,av0.w,av1.x,av1.y,av1.z,av1.w};
            float br[8] = {bv0.x,bv0.y,bv0.z,bv0.w,bv1.x,bv1.y,bv1.z,bv1.w};
            #pragma unroll
            for (int i = 0; i < 8; i++)
                #pragma unroll
                for (int j = 0; j < 8; j++)
                    acc[i][j] = fmaf(ar[i], br[j], acc[i][j]);
        }
        if (t + 1 < nt){
            int nx = cur ^ 1;
            As[nx][la_k+0][la_row] = a0g.x;
            As[nx][la_k+1][la_row] = a0g.y;
            As[nx][la_k+2][la_row] = a0g.z;
            As[nx][la_k+3][la_row] = a0g.w;
            As[nx][la_k+4][la_row] = a1g.x;
            As[nx][la_k+5][la_row] = a1g.y;
            As[nx][la_k+6][la_row] = a1g.z;
            As[nx][la_k+7][la_row] = a1g.w;
            *(float4*)(&Bs[nx][lb_row][lb_col])     = b0g;
            *(float4*)(&Bs[nx][lb_row][lb_col + 4]) = b1g;
            cur = nx;
            __syncthreads();
        }
    }

    if (MODE == 0){
        #pragma unroll
        for (int i = 0; i < 8; i++){
            float* crow = C + (size_t)(by*128 + arow + i) * N + bx*128 + bcol;
            float4 c0 = {acc[i][0], acc[i][1], acc[i][2], acc[i][3]};
            float4 c1 = {acc[i][4], acc[i][5], acc[i][6], acc[i][7]};
            *(float4*)(crow)     = c0;
            *(float4*)(crow + 4) = c1;
        }
    } else {
        #pragma unroll
        for (int i = 0; i < 8; i++){
            int row = by*128 + arow + i;        // l
            int h   = row / 96;
            int w2  = row - h*96;
            bool isx = (w2 < 48);
            int  w   = isx ? w2 : (w2 - 48);
            const float* rsrc = (isx ? rx : ry) + h*48 + w;
            float* od = outp + (isx ? 0 : XFSZ) + h*48 + w;
            #pragma unroll
            for (int j = 0; j < 8; j++){
                int col = bx*128 + bcol + j;    // c
                od[(size_t)col * PLANE] = acc[i][j] + rsrc[(size_t)col * PLANE];
            }
        }
    }
}

// ---------------- 3) causal depthwise conv (K=4) + SiLU ----------------
__global__ void conv_silu_kernel(const float* __restrict__ cw){
    int d = blockIdx.x * 256 + threadIdx.x;   // 0..1279 (grid.x = 5)
    int l = blockIdx.y;                       // 0..4607
    float4 wv = ((const float4*)cw)[d];       // conv_w[d, 0, 0..3]
    const float* xp = g_xz + d;               // xp = xz[:, :1280]
    float acc = wv.w * xp[(size_t)l * DXZ];
    if (l >= 1) acc += wv.z * xp[(size_t)(l-1) * DXZ];
    if (l >= 2) acc += wv.y * xp[(size_t)(l-2) * DXZ];
    if (l >= 3) acc += wv.x * xp[(size_t)(l-3) * DXZ];
    g_xa[(size_t)l * DI + d] = silu_f(acc);
}

// ---------------- 4) proj GEMM split-K: xa(4608x1280) @ W_xproj(1280x56) ----------------
// grid (72, 4): 64-row tiles, 4 K-slices of 320 each; partials in g_pp
__global__ void proj_gemm(const float* __restrict__ A, const float* __restrict__ B){
    __shared__ float As[16][64];
    __shared__ float Bs[16][64];
    int tid = threadIdx.x;
    int by  = blockIdx.x;                 // 0..71
    int ks  = blockIdx.y;                 // 0..3
    int k0b = ks * 320;

    int arow = tid >> 2;                  // 0..63
    int acol = (tid & 3) * 4;             // 0,4,8,12
    const float* Ap = A + (size_t)(by*64 + arow) * DI + k0b + acol;

    float acc[4][4];
    #pragma unroll
    for (int i = 0; i < 4; i++)
        #pragma unroll
        for (int j = 0; j < 4; j++) acc[i][j] = 0.f;

    int ty = tid >> 4, tx = tid & 15;

    for (int k0 = 0; k0 < 320; k0 += 16){
        float4 av = *(const float4*)Ap;
        float bl[4];
        #pragma unroll
        for (int q = 0; q < 4; q++){
            int e = tid*4 + q;
            int r = e >> 6, c = e & 63;
            bl[q] = (c < NPROJ) ? B[(size_t)(k0b + k0 + r) * NPROJ + c] : 0.f;
        }
        __syncthreads();
        As[acol+0][arow] = av.x;
        As[acol+1][arow] = av.y;
        As[acol+2][arow] = av.z;
        As[acol+3][arow] = av.w;
        #pragma unroll
        for (int q = 0; q < 4; q++){
            int e = tid*4 + q;
            Bs[e >> 6][e & 63] = bl[q];
        }
        __syncthreads();
        #pragma unroll
        for (int k = 0; k < 16; k++){
            float ar[4], br[4];
            #pragma unroll
            for (int i = 0; i < 4; i++) ar[i] = As[k][ty*4 + i];
            #pragma unroll
            for (int j = 0; j < 4; j++) br[j] = Bs[k][tx*4 + j];
            #pragma unroll
            for (int i = 0; i < 4; i++)
                #pragma unroll
                for (int j = 0; j < 4; j++)
                    acc[i][j] = fmaf(ar[i], br[j], acc[i][j]);
        }
        __syncthreads();
        Ap += 16;
    }
    float* Cp = g_pp + (size_t)ks * PSLICE;
    #pragma unroll
    for (int i = 0; i < 4; i++){
        int row = by*64 + ty*4 + i;
        #pragma unroll
        for (int j = 0; j < 4; j++){
            int col = tx*4 + j;
            if (col < NPROJ) Cp[(size_t)row * NPROJ + col] = acc[i][j];
        }
    }
}

__global__ void proj_reduce(){
    int i = blockIdx.x * 256 + threadIdx.x;
    if (i < PSLICE){
        g_proj[i] = (g_pp[i] + g_pp[i + PSLICE]) +
                    (g_pp[i + 2*PSLICE] + g_pp[i + 3*PSLICE]);
    }
}

// ---------------- 5) dt = softplus(proj[:, :40] @ W_dt + bias), 8 rows/block ----------------
__global__ void dt_kernel(const float* __restrict__ Wdt, const float* __restrict__ bias){
    __shared__ float pr[8][RANK];
    int t  = threadIdx.x;
    int d  = blockIdx.x * 256 + t;       // grid.x = 5
    int l0 = blockIdx.y * 8;             // grid.y = 576
    if (t < 8 * RANK)
        pr[t / RANK][t % RANK] = g_proj[(size_t)(l0 + t / RANK) * NPROJ + (t % RANK)];
    __syncthreads();

    float acc[8];
    #pragma unroll
    for (int j = 0; j < 8; j++) acc[j] = 0.f;
    for (int k = 0; k < RANK; k++){
        float wv = Wdt[(size_t)k * DI + d];
        #pragma unroll
        for (int j = 0; j < 8; j++) acc[j] = fmaf(pr[j][k], wv, acc[j]);
    }
    float bb = bias[d];
    #pragma unroll
    for (int j = 0; j < 8; j++){
        float v = acc[j] + bb;
        float sp = (v > 20.f) ? v : log1pf(__expf(v));
        g_dt[(size_t)(l0 + j) * DI + d] = sp;
    }
}

// ---------------- 6) selective scan, thread per (d, s) ----------------
__global__ void scan_kernel(const float* __restrict__ A_log, const float* __restrict__ Dp){
    int tid = threadIdx.x;
    int s   = tid & 7;
    int d   = blockIdx.x * 32 + (tid >> 3);   // grid.x = 40

    float Acoef = -__expf(A_log[d*8 + s]);
    float Dval  = Dp[d];

    const float* dtp = g_dt + d;
    const float* xap = g_xa + d;
    const float* zp  = g_xz + DI + d;
    const float* bp  = g_proj + RANK + s;     // B at cols 40..47, C at 48..55
    float* yop = g_yo + d;

    float h = 0.f;
    for (int l = 0; l < LSEQ; l++){
        float dtv = __ldg(dtp);
        float xav = __ldg(xap);
        float Bv  = __ldg(bp);
        float Cv  = __ldg(bp + 8);
        float dA  = __expf(dtv * Acoef);
        h = fmaf(dA, h, dtv * xav * Bv);
        float yv = h * Cv;
        yv += __shfl_xor_sync(0xffffffffu, yv, 1);
        yv += __shfl_xor_sync(0xffffffffu, yv, 2);
        yv += __shfl_xor_sync(0xffffffffu, yv, 4);
        if (s == 0){
            float zv = __ldg(zp);
            yop[0] = (yv + xav * Dval) * silu_f(zv);
        }
        dtp += DI; xap += DI; bp += NPROJ; zp += DXZ; yop += DI;
    }
}

// ---------------- launch ----------------
extern "C" void kernel_launch(void* const* d_in, const int* in_sizes, int n_in,
                              void* d_out, int out_size){
    const float* x       = (const float*)d_in[0];
    const float* y       = (const float*)d_in[1];
    const float* ln_g    = (const float*)d_in[2];
    const float* ln_b    = (const float*)d_in[3];
    const float* W_in    = (const float*)d_in[4];
    const float* conv_w  = (const float*)d_in[5];
    const float* W_xproj = (const float*)d_in[6];
    const float* W_dt    = (const float*)d_in[7];
    const float* dt_bias = (const float*)d_in[8];
    const float* A_log   = (const float*)d_in[9];
    const float* Dp      = (const float*)d_in[10];
    const float* W_out   = (const float*)d_in[11];
    float* out = (float*)d_out;

    float *xn_p, *xz_p, *xa_p, *yo_p;
    cudaGetSymbolAddress((void**)&xn_p, g_xn);
    cudaGetSymbolAddress((void**)&xz_p, g_xz);
    cudaGetSymbolAddress((void**)&xa_p, g_xa);
    cudaGetSymbolAddress((void**)&yo_p, g_yo);

    // 1) gather + layernorm
    ln_kernel<<<LSEQ, 256>>>(x, y, ln_g, ln_b);

    // 2) xz = xn @ W_in   (4608 x 2560 x 640)
    sgemm_db<0><<<dim3(DXZ/128, LSEQ/128), 256>>>(
        xn_p, W_in, xz_p, CDIM, DXZ, nullptr, nullptr, nullptr);

    // 3) xa = silu(causal_dwconv(xp))
    conv_silu_kernel<<<dim3(DI/256, LSEQ), 256>>>(conv_w);

    // 4) proj = xa @ W_xproj   (4608 x 56 x 1280), split-K=4
    proj_gemm<<<dim3(LSEQ/64, 4), 256>>>(xa_p, W_xproj);
    proj_reduce<<<(PSLICE + 255)/256, 256>>>();

    // 5) dt
    dt_kernel<<<dim3(DI/256, LSEQ/8), 256>>>(W_dt, dt_bias);

    // 6) scan + gating
    scan_kernel<<<DI*8/256, 256>>>(A_log, Dp);

    // 7) out = yo @ W_out + seq, scattered into (xf | yf)
    sgemm_db<1><<<dim3(CDIM/128, LSEQ/128), 256>>>(
        yo_p, W_out, nullptr, DI, CDIM, x, y, out);
}

// round 3
// speedup vs baseline: 6.0193x; 6.0193x over previous
#include <cuda_runtime.h>
#include <cuda_bf16.h>

#define LSEQ 4608
#define CDIM 640
#define DI   1280
#define DXZ  2560
#define NPROJ 56
#define RANK  40
#define PLANE 2304          // 48*48
#define XFSZ  (640*2304)    // elements in xf output
#define PSLICE (LSEQ*NPROJ) // 258048
#define NCHUNK 72
#define CLEN   64           // 72*64 = 4608
#define DS     (DI*8)       // 10240 (d,s) pairs

// ---------------- scratch (static device allocations; no cudaMalloc) ----------------
__device__ float g_xn  [LSEQ*CDIM];   // layernorm output
__device__ float g_xz  [LSEQ*DXZ];    // xn @ W_in  (xp | z)
__device__ float g_xa  [LSEQ*DI];     // silu(conv(xp))
__device__ float g_proj[LSEQ*NPROJ];  // xa @ W_xproj  (dtin | B | C)
__device__ float g_pp  [4*PSLICE];    // split-K partials for proj
__device__ float g_dt  [LSEQ*DI];     // softplus(proj[:, :40] @ W_dt + bias)
__device__ float g_yo  [LSEQ*DI];     // gated ssm output
__device__ float g_cP  [NCHUNK*DS];   // per-chunk state decay product
__device__ float g_cH  [NCHUNK*DS];   // per-chunk local final state
__device__ float g_h0  [NCHUNK*DS];   // per-chunk initial state (fixed up)

// ---------------- helpers ----------------
__device__ __forceinline__ float silu_f(float v){
    return v / (1.0f + __expf(-v));
}

// ---------------- 1) gather + layernorm ----------------
__global__ void ln_kernel(const float* __restrict__ x, const float* __restrict__ yy,
                          const float* __restrict__ g, const float* __restrict__ b){
    int l  = blockIdx.x;
    int h  = l / 96;
    int w2 = l - h * 96;
    const float* src = (w2 < 48) ? (x + h*48 + w2) : (yy + h*48 + (w2-48));
    int t = threadIdx.x;   // 256 threads

    float v0 = src[(size_t)t       * PLANE];
    float v1 = src[(size_t)(t+256) * PLANE];
    float v2 = (t < 128) ? src[(size_t)(t+512) * PLANE] : 0.f;

    float s  = v0 + v1 + v2;
    float s2 = v0*v0 + v1*v1 + v2*v2;
    #pragma unroll
    for (int o = 16; o > 0; o >>= 1){
        s  += __shfl_xor_sync(0xffffffffu, s , o);
        s2 += __shfl_xor_sync(0xffffffffu, s2, o);
    }
    __shared__ float rs[8], rs2[8];
    int wid = t >> 5, lid = t & 31;
    if (lid == 0){ rs[wid] = s; rs2[wid] = s2; }
    __syncthreads();
    if (t == 0){
        float a = 0.f, a2 = 0.f;
        #pragma unroll
        for (int i = 0; i < 8; i++){ a += rs[i]; a2 += rs2[i]; }
        rs[0] = a; rs2[0] = a2;
    }
    __syncthreads();
    float mean = rs[0]  * (1.f/640.f);
    float var  = rs2[0] * (1.f/640.f) - mean*mean;
    float inv  = rsqrtf(var + 1e-5f);

    float* dst = g_xn + (size_t)l * CDIM;
    dst[t]       = (v0 - mean) * inv * g[t]       + b[t];
    dst[t + 256] = (v1 - mean) * inv * g[t + 256] + b[t + 256];
    if (t < 128)
        dst[t + 512] = (v2 - mean) * inv * g[t + 512] + b[t + 512];
}

// ---------------- 2/7) 128x128 double-buffered BK=16 SGEMM ----------------
template<int MODE>
__global__ void __launch_bounds__(256)
sgemm_db(const float* __restrict__ A, const float* __restrict__ B,
         float* __restrict__ C, int K, int N,
         const float* __restrict__ rx, const float* __restrict__ ry,
         float* __restrict__ outp){
    __shared__ float As[2][16][128];
    __shared__ float Bs[2][16][128];
    int tid = threadIdx.x;
    int bx = blockIdx.x, by = blockIdx.y;
    int wid  = tid >> 5, lane = tid & 31;
    int wr = wid >> 2, wc = wid & 3;       // warp grid 2 x 4  (64 x 32 warp tiles)
    int lr = lane >> 2, lc = lane & 3;     // lane grid 8 x 4  (8 x 8 thread tiles)
    int arow = wr*64 + lr*8;
    int bcol = wc*32 + lc*8;

    int la_row = tid >> 1;                 // 0..127
    int la_k   = (tid & 1) * 8;            // 0 or 8
    int lb_row = tid >> 4;                 // 0..15
    int lb_col = (tid & 15) * 8;

    const float* Ap = A + (size_t)(by*128 + la_row) * K + la_k;
    const float* Bp = B + (size_t)lb_row * N + bx*128 + lb_col;

    float4 a0g = *(const float4*)Ap;
    float4 a1g = *(const float4*)(Ap + 4);
    float4 b0g = *(const float4*)Bp;
    float4 b1g = *(const float4*)(Bp + 4);

    float acc[8][8];
    #pragma unroll
    for (int i = 0; i < 8; i++)
        #pragma unroll
        for (int j = 0; j < 8; j++) acc[i][j] = 0.f;

    As[0][la_k+0][la_row] = a0g.x;
    As[0][la_k+1][la_row] = a0g.y;
    As[0][la_k+2][la_row] = a0g.z;
    As[0][la_k+3][la_row] = a0g.w;
    As[0][la_k+4][la_row] = a1g.x;
    As[0][la_k+5][la_row] = a1g.y;
    As[0][la_k+6][la_row] = a1g.z;
    As[0][la_k+7][la_row] = a1g.w;
    *(float4*)(&Bs[0][lb_row][lb_col])     = b0g;
    *(float4*)(&Bs[0][lb_row][lb_col + 4]) = b1g;
    __syncthreads();

    int nt = K / 16;
    int cur = 0;
    for (int t = 0; t < nt; t++){
        if (t + 1 < nt){
            Ap += 16;
            Bp += (size_t)16 * N;
            a0g = *(const float4*)Ap;
            a1g = *(const float4*)(Ap + 4);
            b0g = *(const float4*)Bp;
            b1g = *(const float4*)(Bp + 4);
        }
        #pragma unroll
        for (int k = 0; k < 16; k++){
            float4 av0 = *(const float4*)(&As[cur][k][arow]);
            float4 av1 = *(const float4*)(&As[cur][k][arow + 4]);
            float4 bv0 = *(const float4*)(&Bs[cur][k][bcol]);
            float4 bv1 = *(const float4*)(&Bs[cur][k][bcol + 4]);
            float ar[8] = {av0.x,av0.y,av0.z,av0.w,av1.x,av1.y,av1.z,av1.w};
            float br[8] = {bv0.x,bv0.y,bv0.z,bv0.w,bv1.x,bv1.y,bv1.z,bv1.w};
            #pragma unroll
            for (int i = 0; i < 8; i++)
                #pragma unroll
                for (int j = 0; j < 8; j++)
                    acc[i][j] = fmaf(ar[i], br[j], acc[i][j]);
        }
        if (t + 1 < nt){
            int nx = cur ^ 1;
            As[nx][la_k+0][la_row] = a0g.x;
            As[nx][la_k+1][la_row] = a0g.y;
            As[nx][la_k+2][la_row] = a0g.z;
            As[nx][la_k+3][la_row] = a0g.w;
            As[nx][la_k+4][la_row] = a1g.x;
            As[nx][la_k+5][la_row] = a1g.y;
            As[nx][la_k+6][la_row] = a1g.z;
            As[nx][la_k+7][la_row] = a1g.w;
            *(float4*)(&Bs[nx][lb_row][lb_col])     = b0g;
            *(float4*)(&Bs[nx][lb_row][lb_col + 4]) = b1g;
            cur = nx;
            __syncthreads();
        }
    }

    if (MODE == 0){
        #pragma unroll
        for (int i = 0; i < 8; i++){
            float* crow = C + (size_t)(by*128 + arow + i) * N + bx*128 + bcol;
            float4 c0 = {acc[i][0], acc[i][1], acc[i][2], acc[i][3]};
            float4 c1 = {acc[i][4], acc[i][5], acc[i][6], acc[i][7]};
            *(float4*)(crow)     = c0;
            *(float4*)(crow + 4) = c1;
        }
    } else {
        #pragma unroll
        for (int i = 0; i < 8; i++){
            int row = by*128 + arow + i;        // l
            int h   = row / 96;
            int w2  = row - h*96;
            bool isx = (w2 < 48);
            int  w   = isx ? w2 : (w2 - 48);
            const float* rsrc = (isx ? rx : ry) + h*48 + w;
            float* od = outp + (isx ? 0 : XFSZ) + h*48 + w;
            #pragma unroll
            for (int j = 0; j < 8; j++){
                int col = bx*128 + bcol + j;    // c
                od[(size_t)col * PLANE] = acc[i][j] + rsrc[(size_t)col * PLANE];
            }
        }
    }
}

// ---------------- 3) causal depthwise conv (K=4) + SiLU ----------------
__global__ void conv_silu_kernel(const float* __restrict__ cw){
    int d = blockIdx.x * 256 + threadIdx.x;   // 0..1279 (grid.x = 5)
    int l = blockIdx.y;                       // 0..4607
    float4 wv = ((const float4*)cw)[d];       // conv_w[d, 0, 0..3]
    const float* xp = g_xz + d;               // xp = xz[:, :1280]
    float acc = wv.w * xp[(size_t)l * DXZ];
    if (l >= 1) acc += wv.z * xp[(size_t)(l-1) * DXZ];
    if (l >= 2) acc += wv.y * xp[(size_t)(l-2) * DXZ];
    if (l >= 3) acc += wv.x * xp[(size_t)(l-3) * DXZ];
    g_xa[(size_t)l * DI + d] = silu_f(acc);
}

// ---------------- 4) proj GEMM split-K: xa(4608x1280) @ W_xproj(1280x56) ----------------
__global__ void proj_gemm(const float* __restrict__ A, const float* __restrict__ B){
    __shared__ float As[16][64];
    __shared__ float Bs[16][64];
    int tid = threadIdx.x;
    int by  = blockIdx.x;                 // 0..71
    int ks  = blockIdx.y;                 // 0..3
    int k0b = ks * 320;

    int arow = tid >> 2;                  // 0..63
    int acol = (tid & 3) * 4;             // 0,4,8,12
    const float* Ap = A + (size_t)(by*64 + arow) * DI + k0b + acol;

    float acc[4][4];
    #pragma unroll
    for (int i = 0; i < 4; i++)
        #pragma unroll
        for (int j = 0; j < 4; j++) acc[i][j] = 0.f;

    int ty = tid >> 4, tx = tid & 15;

    for (int k0 = 0; k0 < 320; k0 += 16){
        float4 av = *(const float4*)Ap;
        float bl[4];
        #pragma unroll
        for (int q = 0; q < 4; q++){
            int e = tid*4 + q;
            int r = e >> 6, c = e & 63;
            bl[q] = (c < NPROJ) ? B[(size_t)(k0b + k0 + r) * NPROJ + c] : 0.f;
        }
        __syncthreads();
        As[acol+0][arow] = av.x;
        As[acol+1][arow] = av.y;
        As[acol+2][arow] = av.z;
        As[acol+3][arow] = av.w;
        #pragma unroll
        for (int q = 0; q < 4; q++){
            int e = tid*4 + q;
            Bs[e >> 6][e & 63] = bl[q];
        }
        __syncthreads();
        #pragma unroll
        for (int k = 0; k < 16; k++){
            float ar[4], br[4];
            #pragma unroll
            for (int i = 0; i < 4; i++) ar[i] = As[k][ty*4 + i];
            #pragma unroll
            for (int j = 0; j < 4; j++) br[j] = Bs[k][tx*4 + j];
            #pragma unroll
            for (int i = 0; i < 4; i++)
                #pragma unroll
                for (int j = 0; j < 4; j++)
                    acc[i][j] = fmaf(ar[i], br[j], acc[i][j]);
        }
        __syncthreads();
        Ap += 16;
    }
    float* Cp = g_pp + (size_t)ks * PSLICE;
    #pragma unroll
    for (int i = 0; i < 4; i++){
        int row = by*64 + ty*4 + i;
        #pragma unroll
        for (int j = 0; j < 4; j++){
            int col = tx*4 + j;
            if (col < NPROJ) Cp[(size_t)row * NPROJ + col] = acc[i][j];
        }
    }
}

__global__ void proj_reduce(){
    int i = blockIdx.x * 256 + threadIdx.x;
    if (i < PSLICE){
        g_proj[i] = (g_pp[i] + g_pp[i + PSLICE]) +
                    (g_pp[i + 2*PSLICE] + g_pp[i + 3*PSLICE]);
    }
}

// ---------------- 5) dt = softplus(proj[:, :40] @ W_dt + bias), 8 rows/block ----------------
__global__ void dt_kernel(const float* __restrict__ Wdt, const float* __restrict__ bias){
    __shared__ float pr[8][RANK];
    int t  = threadIdx.x;
    int d  = blockIdx.x * 256 + t;       // grid.x = 5
    int l0 = blockIdx.y * 8;             // grid.y = 576
    if (t < 8 * RANK)
        pr[t / RANK][t % RANK] = g_proj[(size_t)(l0 + t / RANK) * NPROJ + (t % RANK)];
    __syncthreads();

    float acc[8];
    #pragma unroll
    for (int j = 0; j < 8; j++) acc[j] = 0.f;
    for (int k = 0; k < RANK; k++){
        float wv = Wdt[(size_t)k * DI + d];
        #pragma unroll
        for (int j = 0; j < 8; j++) acc[j] = fmaf(pr[j][k], wv, acc[j]);
    }
    float bb = bias[d];
    #pragma unroll
    for (int j = 0; j < 8; j++){
        float v = acc[j] + bb;
        float sp = (v > 20.f) ? v : log1pf(__expf(v));
        g_dt[(size_t)(l0 + j) * DI + d] = sp;
    }
}

// ---------------- 6) chunked parallel selective scan ----------------
// Phase A: per (d, chunk), local scan of 8 states from h=0; emit chunk decay P_s
// and final local state H_s.  dA_s = exp(dt*Ac_s) = e1^(s+1) with e1 = exp(dt*Ac_0)
// (integer-ratio fast path; generic expf fallback).
__global__ void __launch_bounds__(256)
scan_phaseA(const float* __restrict__ A_log){
    int t = threadIdx.x;
    int d = blockIdx.x * 256 + t;        // grid.x = 5
    int g = blockIdx.y;                  // 0..71

    float Ac[8];
    #pragma unroll
    for (int s = 0; s < 8; s++) Ac[s] = -__expf(A_log[d*8 + s]);
    bool fast = true;
    #pragma unroll
    for (int s = 0; s < 8; s++){
        float r = Ac[s] / Ac[0];
        if (fabsf(r - (float)(s+1)) > 1e-3f) fast = false;
    }

    float h[8];
    #pragma unroll
    for (int s = 0; s < 8; s++) h[s] = 0.f;
    float Etot = 1.f;

    const float* dtp = g_dt   + (size_t)(g*CLEN) * DI + d;
    const float* xap = g_xa   + (size_t)(g*CLEN) * DI + d;
    const float* bp  = g_proj + (size_t)(g*CLEN) * NPROJ + RANK;

    if (fast){
        for (int l = 0; l < CLEN; l++){
            float dtv = *dtp, xav = *xap;
            float e1 = __expf(dtv * Ac[0]);
            float db = dtv * xav;
            Etot *= e1;
            float p = 1.f;
            #pragma unroll
            for (int s = 0; s < 8; s++){
                p *= e1;
                h[s] = fmaf(p, h[s], db * __ldg(bp + s));
            }
            dtp += DI; xap += DI; bp += NPROJ;
        }
        size_t base = (size_t)g * DS + d*8;
        float P = 1.f;
        #pragma unroll
        for (int s = 0; s < 8; s++){
            P *= Etot;
            g_cP[base + s] = P;
            g_cH[base + s] = h[s];
        }
    } else {
        float Ps[8];
        #pragma unroll
        for (int s = 0; s < 8; s++) Ps[s] = 1.f;
        for (int l = 0; l < CLEN; l++){
            float dtv = *dtp, xav = *xap;
            float db = dtv * xav;
            #pragma unroll
            for (int s = 0; s < 8; s++){
                float dA = __expf(dtv * Ac[s]);
                Ps[s] *= dA;
                h[s] = fmaf(dA, h[s], db * __ldg(bp + s));
            }
            dtp += DI; xap += DI; bp += NPROJ;
        }
        size_t base = (size_t)g * DS + d*8;
        #pragma unroll
        for (int s = 0; s < 8; s++){
            g_cP[base + s] = Ps[s];
            g_cH[base + s] = h[s];
        }
    }
}

// Phase B: sequential fix-up across chunks per (d,s): h0[g] = P[g-1]*h0[g-1] + H[g-1]
__global__ void scan_phaseB(){
    int idx = blockIdx.x * 256 + threadIdx.x;   // 0..10239 (40 blocks)
    float h = 0.f;
    for (int g = 0; g < NCHUNK; g++){
        size_t o = (size_t)g * DS + idx;
        g_h0[o] = h;
        h = fmaf(g_cP[o], h, g_cH[o]);
    }
}

// Phase C: re-run local scans from correct h0, produce yo = (sum_s h*C + xa*D)*silu(z)
__global__ void __launch_bounds__(256)
scan_phaseC(const float* __restrict__ A_log, const float* __restrict__ Dp){
    int t = threadIdx.x;
    int d = blockIdx.x * 256 + t;
    int g = blockIdx.y;

    float Ac[8];
    #pragma unroll
    for (int s = 0; s < 8; s++) Ac[s] = -__expf(A_log[d*8 + s]);
    bool fast = true;
    #pragma unroll
    for (int s = 0; s < 8; s++){
        float r = Ac[s] / Ac[0];
        if (fabsf(r - (float)(s+1)) > 1e-3f) fast = false;
    }

    float h[8];
    size_t hb = (size_t)g * DS + d*8;
    #pragma unroll
    for (int s = 0; s < 8; s++) h[s] = g_h0[hb + s];
    float Dval = Dp[d];

    const float* dtp = g_dt   + (size_t)(g*CLEN) * DI + d;
    const float* xap = g_xa   + (size_t)(g*CLEN) * DI + d;
    const float* zp  = g_xz   + (size_t)(g*CLEN) * DXZ + DI + d;
    const float* bp  = g_proj + (size_t)(g*CLEN) * NPROJ + RANK;
    float* yop = g_yo + (size_t)(g*CLEN) * DI + d;

    if (fast){
        for (int l = 0; l < CLEN; l++){
            float dtv = *dtp, xav = *xap;
            float e1 = __expf(dtv * Ac[0]);
            float db = dtv * xav;
            float p = 1.f, yv = 0.f;
            #pragma unroll
            for (int s = 0; s < 8; s++){
                p *= e1;
                h[s] = fmaf(p, h[s], db * __ldg(bp + s));
                yv = fmaf(h[s], __ldg(bp + 8 + s), yv);
            }
            float zv = *zp;
            *yop = (yv + xav * Dval) * silu_f(zv);
            dtp += DI; xap += DI; zp += DXZ; bp += NPROJ; yop += DI;
        }
    } else {
        for (int l = 0; l < CLEN; l++){
            float dtv = *dtp, xav = *xap;
            float db = dtv * xav;
            float yv = 0.f;
            #pragma unroll
            for (int s = 0; s < 8; s++){
                float dA = __expf(dtv * Ac[s]);
                h[s] = fmaf(dA, h[s], db * __ldg(bp + s));
                yv = fmaf(h[s], __ldg(bp + 8 + s), yv);
            }
            float zv = *zp;
            *yop = (yv + xav * Dval) * silu_f(zv);
            dtp += DI; xap += DI; zp += DXZ; bp += NPROJ; yop += DI;
        }
    }
}

// ---------------- launch ----------------
extern "C" void kernel_launch(void* const* d_in, const int* in_sizes, int n_in,
                              void* d_out, int out_size){
    const float* x       = (const float*)d_in[0];
    const float* y       = (const float*)d_in[1];
    const float* ln_g    = (const float*)d_in[2];
    const float* ln_b    = (const float*)d_in[3];
    const float* W_in    = (const float*)d_in[4];
    const float* conv_w  = (const float*)d_in[5];
    const float* W_xproj = (const float*)d_in[6];
    const float* W_dt    = (const float*)d_in[7];
    const float* dt_bias = (const float*)d_in[8];
    const float* A_log   = (const float*)d_in[9];
    const float* Dp      = (const float*)d_in[10];
    const float* W_out   = (const float*)d_in[11];
    float* out = (float*)d_out;

    float *xn_p, *xz_p, *xa_p, *yo_p;
    cudaGetSymbolAddress((void**)&xn_p, g_xn);
    cudaGetSymbolAddress((void**)&xz_p, g_xz);
    cudaGetSymbolAddress((void**)&xa_p, g_xa);
    cudaGetSymbolAddress((void**)&yo_p, g_yo);

    // 1) gather + layernorm
    ln_kernel<<<LSEQ, 256>>>(x, y, ln_g, ln_b);

    // 2) xz = xn @ W_in   (4608 x 2560 x 640)
    sgemm_db<0><<<dim3(DXZ/128, LSEQ/128), 256>>>(
        xn_p, W_in, xz_p, CDIM, DXZ, nullptr, nullptr, nullptr);

    // 3) xa = silu(causal_dwconv(xp))
    conv_silu_kernel<<<dim3(DI/256, LSEQ), 256>>>(conv_w);

    // 4) proj = xa @ W_xproj   (4608 x 56 x 1280), split-K=4
    proj_gemm<<<dim3(LSEQ/64, 4), 256>>>(xa_p, W_xproj);
    proj_reduce<<<(PSLICE + 255)/256, 256>>>();

    // 5) dt
    dt_kernel<<<dim3(DI/256, LSEQ/8), 256>>>(W_dt, dt_bias);

    // 6) chunked parallel scan + gating
    scan_phaseA<<<dim3(DI/256, NCHUNK), 256>>>(A_log);
    scan_phaseB<<<DS/256, 256>>>();
    scan_phaseC<<<dim3(DI/256, NCHUNK), 256>>>(A_log, Dp);

    // 7) out = yo @ W_out + seq, scattered into (xf | yf)
    sgemm_db<1><<<dim3(CDIM/128, LSEQ/128), 256>>>(
        yo_p, W_out, nullptr, DI, CDIM, x, y, out);
}

// round 6
// speedup vs baseline: 8.8278x; 1.4666x over previous
#include <cuda_runtime.h>
#include <cuda_bf16.h>
#include <mma.h>
#include <cstdint>

using namespace nvcuda;

#define LSEQ 4608
#define CDIM 640
#define DI   1280
#define DXZ  2560
#define NPROJ 56
#define RANK  40
#define PLANE 2304          // 48*48
#define XFSZ  (640*2304)
#define PSLICE (LSEQ*NPROJ)
#define NCHUNK 72
#define CLEN   64
#define DS     (DI*8)

// ---------------- scratch ----------------
__device__ float g_xz  [LSEQ*DXZ];
__device__ float g_xa  [LSEQ*DI];
__device__ float g_proj[LSEQ*NPROJ];
__device__ float g_pp  [8*PSLICE];
__device__ float g_dt  [LSEQ*DI];
__device__ float g_cP  [NCHUNK*DS];
__device__ float g_cH  [NCHUNK*DS];
__device__ float g_h0  [NCHUNK*DS];
// bf16 hi/lo operands for tensor-core GEMMs (16B-aligned for cp.async)
__device__ __align__(256) __nv_bfloat16 g_a1hi[LSEQ*CDIM], g_a1lo[LSEQ*CDIM]; // ln(seq)
__device__ __align__(256) __nv_bfloat16 g_b1hi[DXZ*CDIM],  g_b1lo[DXZ*CDIM];  // W_in^T  [2560,640]
__device__ __align__(256) __nv_bfloat16 g_a2hi[LSEQ*DI],   g_a2lo[LSEQ*DI];   // yo
__device__ __align__(256) __nv_bfloat16 g_b2hi[CDIM*DI],   g_b2lo[CDIM*DI];   // W_out^T [640,1280]

// ---------------- helpers ----------------
#define CP_ASYNC16(dst, src) \
    asm volatile("cp.async.cg.shared.global [%0], [%1], 16;" :: "r"(dst), "l"(src) : "memory")
#define CP_COMMIT() asm volatile("cp.async.commit_group;" ::: "memory")
#define CP_WAIT(n)  asm volatile("cp.async.wait_group %0;" :: "n"(n) : "memory")

__device__ __forceinline__ uint32_t smem_u32(const void* p){
    uint32_t a;
    asm("{ .reg .u64 t; cvta.to.shared.u64 t, %1; cvt.u32.u64 %0, t; }" : "=r"(a) : "l"(p));
    return a;
}
__device__ __forceinline__ float silu_f(float v){ return v / (1.0f + __expf(-v)); }
__device__ __forceinline__ void split_store(float v, __nv_bfloat16* hi, __nv_bfloat16* lo, size_t off){
    __nv_bfloat16 h = __float2bfloat16(v);
    hi[off] = h;
    lo[off] = __float2bfloat16(v - __bfloat162float(h));
}

// ---------------- 1) gather + layernorm -> bf16 hi/lo ----------------
__global__ void ln_kernel(const float* __restrict__ x, const float* __restrict__ yy,
                          const float* __restrict__ g, const float* __restrict__ b){
    int l  = blockIdx.x;
    int h  = l / 96;
    int w2 = l - h * 96;
    const float* src = (w2 < 48) ? (x + h*48 + w2) : (yy + h*48 + (w2-48));
    int t = threadIdx.x;   // 256

    float v0 = src[(size_t)t       * PLANE];
    float v1 = src[(size_t)(t+256) * PLANE];
    float v2 = (t < 128) ? src[(size_t)(t+512) * PLANE] : 0.f;

    float s  = v0 + v1 + v2;
    float s2 = v0*v0 + v1*v1 + v2*v2;
    #pragma unroll
    for (int o = 16; o > 0; o >>= 1){
        s  += __shfl_xor_sync(0xffffffffu, s , o);
        s2 += __shfl_xor_sync(0xffffffffu, s2, o);
    }
    __shared__ float rs[8], rs2[8];
    int wid = t >> 5, lid = t & 31;
    if (lid == 0){ rs[wid] = s; rs2[wid] = s2; }
    __syncthreads();
    if (t == 0){
        float a = 0.f, a2 = 0.f;
        #pragma unroll
        for (int i = 0; i < 8; i++){ a += rs[i]; a2 += rs2[i]; }
        rs[0] = a; rs2[0] = a2;
    }
    __syncthreads();
    float mean = rs[0]  * (1.f/640.f);
    float var  = rs2[0] * (1.f/640.f) - mean*mean;
    float inv  = rsqrtf(var + 1e-5f);

    size_t base = (size_t)l * CDIM;
    float o0 = (v0 - mean) * inv * g[t]       + b[t];
    float o1 = (v1 - mean) * inv * g[t + 256] + b[t + 256];
    split_store(o0, g_a1hi, g_a1lo, base + t);
    split_store(o1, g_a1hi, g_a1lo, base + t + 256);
    if (t < 128){
        float o2 = (v2 - mean) * inv * g[t + 512] + b[t + 512];
        split_store(o2, g_a1hi, g_a1lo, base + t + 512);
    }
}

// ---------------- weight transpose + bf16 split: W[K,N] -> Wt[n*K+k] ----------------
__global__ void transpose_split(const float* __restrict__ W,
                                __nv_bfloat16* __restrict__ hi, __nv_bfloat16* __restrict__ lo,
                                int K, int N){
    __shared__ float tile[32][33];
    int n0 = blockIdx.x * 32, k0 = blockIdx.y * 32;
    int tx = threadIdx.x, ty = threadIdx.y;   // (32, 8)
    #pragma unroll
    for (int i = 0; i < 4; i++)
        tile[ty + 8*i][tx] = W[(size_t)(k0 + ty + 8*i) * N + n0 + tx];
    __syncthreads();
    #pragma unroll
    for (int i = 0; i < 4; i++){
        float v = tile[tx][ty + 8*i];
        size_t o = (size_t)(n0 + ty + 8*i) * K + k0 + tx;
        __nv_bfloat16 h = __float2bfloat16(v);
        hi[o] = h;
        lo[o] = __float2bfloat16(v - __bfloat162float(h));
    }
}

// ---------------- wmma bf16-split GEMM: C[M,Nc] = A[M,K] @ B[Nc,K]^T ----------------
// 3 terms: Ahi*Bhi + Alo*Bhi + Ahi*Blo, fp32 accumulators.
// Block tile 128x128, warps 4x2 (32x64 each), BK=32, cp.async double buffer.
#define LDS_E 56                         // bf16 smem row stride (x2 = 112B, mult of 16B)
#define STG_LD 68                        // fp32 staging ldm, MUST be multiple of 4
#define TILE_BYTES (128*LDS_E*2)         // 14336
#define GEMM_SMEM  (8*TILE_BYTES)        // 114688

template<int MODE>
__global__ void __launch_bounds__(256, 1)
gemm_wmma(const __nv_bfloat16* __restrict__ Ahi, const __nv_bfloat16* __restrict__ Alo,
          const __nv_bfloat16* __restrict__ Bhi, const __nv_bfloat16* __restrict__ Blo,
          float* __restrict__ C, int K, int Nc,
          const float* __restrict__ rx, const float* __restrict__ ry,
          float* __restrict__ outp){
    extern __shared__ __align__(32) char smem[];
    uint32_t sbase = smem_u32(smem);
    int tid = threadIdx.x;
    int wid = tid >> 5, lane = tid & 31;
    int wr = wid & 3, wc = wid >> 2;          // 4 x 2 warp grid
    int n0 = blockIdx.x * 128, m0 = blockIdx.y * 128;

    const char* srcs[4] = {
        (const char*)(Ahi + (size_t)m0 * K), (const char*)(Alo + (size_t)m0 * K),
        (const char*)(Bhi + (size_t)n0 * K), (const char*)(Blo + (size_t)n0 * K) };
    int rowbytes = K * 2;
    int nstage = K / 32;

    wmma::fragment<wmma::accumulator, 16, 16, 16, float> acc[2][4];
    #pragma unroll
    for (int i = 0; i < 2; i++)
        #pragma unroll
        for (int j = 0; j < 4; j++) wmma::fill_fragment(acc[i][j], 0.f);

    auto load_stage = [&](int st, int k0bytes){
        #pragma unroll
        for (int tl = 0; tl < 4; tl++){
            const char* bp = srcs[tl] + k0bytes;
            uint32_t tb = sbase + (uint32_t)((st*4 + tl) * TILE_BYTES);
            #pragma unroll
            for (int j = 0; j < 2; j++){
                int cidx = tid + j*256;          // 0..511
                int row = cidx >> 2, c = cidx & 3;
                CP_ASYNC16(tb + (uint32_t)(row*(LDS_E*2) + c*16),
                           bp + (size_t)row * rowbytes + c*16);
            }
        }
        CP_COMMIT();
    };

    load_stage(0, 0);

    for (int t = 0; t < nstage; t++){
        int s = t & 1;
        if (t + 1 < nstage){
            load_stage(s ^ 1, (t+1)*64);
            CP_WAIT(1);
        } else {
            CP_WAIT(0);
        }
        __syncthreads();

        const __nv_bfloat16* As_h = (const __nv_bfloat16*)(smem + (s*4 + 0)*TILE_BYTES);
        const __nv_bfloat16* As_l = (const __nv_bfloat16*)(smem + (s*4 + 1)*TILE_BYTES);
        const __nv_bfloat16* Bs_h = (const __nv_bfloat16*)(smem + (s*4 + 2)*TILE_BYTES);
        const __nv_bfloat16* Bs_l = (const __nv_bfloat16*)(smem + (s*4 + 3)*TILE_BYTES);

        #pragma unroll
        for (int kf = 0; kf < 2; kf++){
            wmma::fragment<wmma::matrix_a, 16, 16, 16, __nv_bfloat16, wmma::row_major> ah[2], al[2];
            wmma::fragment<wmma::matrix_b, 16, 16, 16, __nv_bfloat16, wmma::col_major> bh[4], bl[4];
            #pragma unroll
            for (int i = 0; i < 2; i++){
                int r = wr*32 + i*16;
                wmma::load_matrix_sync(ah[i], As_h + r*LDS_E + kf*16, LDS_E);
                wmma::load_matrix_sync(al[i], As_l + r*LDS_E + kf*16, LDS_E);
            }
            #pragma unroll
            for (int j = 0; j < 4; j++){
                int c = wc*64 + j*16;
                wmma::load_matrix_sync(bh[j], Bs_h + c*LDS_E + kf*16, LDS_E);
                wmma::load_matrix_sync(bl[j], Bs_l + c*LDS_E + kf*16, LDS_E);
            }
            #pragma unroll
            for (int i = 0; i < 2; i++)
                #pragma unroll
                for (int j = 0; j < 4; j++){
                    wmma::mma_sync(acc[i][j], ah[i], bh[j], acc[i][j]);
                    wmma::mma_sync(acc[i][j], al[i], bh[j], acc[i][j]);
                    wmma::mma_sync(acc[i][j], ah[i], bl[j], acc[i][j]);
                }
        }
        __syncthreads();
    }

    if (MODE == 0){
        #pragma unroll
        for (int i = 0; i < 2; i++)
            #pragma unroll
            for (int j = 0; j < 4; j++){
                float* cp = C + (size_t)(m0 + wr*32 + i*16) * Nc + n0 + wc*64 + j*16;
                wmma::store_matrix_sync(cp, acc[i][j], Nc, wmma::mem_row_major);
            }
    } else {
        // stage 32x64 warp tile into padded smem (legal ldm), then coalesced scatter
        float* stg = (float*)smem + (size_t)wid * (32*STG_LD);
        #pragma unroll
        for (int i = 0; i < 2; i++)
            #pragma unroll
            for (int j = 0; j < 4; j++)
                wmma::store_matrix_sync(stg + i*16*STG_LD + j*16, acc[i][j], STG_LD,
                                        wmma::mem_row_major);
        __syncwarp();

        int row = m0 + wr*32 + lane;          // lane = local row
        int h   = row / 96;
        int w2  = row - h*96;
        bool isx = (w2 < 48);
        int  w   = isx ? w2 : (w2 - 48);
        const float* rsrc = (isx ? rx : ry) + h*48 + w;
        float* od = outp + (isx ? 0 : XFSZ) + h*48 + w;
        #pragma unroll 8
        for (int j = 0; j < 64; j++){
            int col = n0 + wc*64 + j;
            od[(size_t)col * PLANE] = stg[lane*STG_LD + j] + rsrc[(size_t)col * PLANE];
        }
    }
}

// ---------------- 3) causal depthwise conv (K=4) + SiLU ----------------
__global__ void conv_silu_kernel(const float* __restrict__ cw){
    int d = blockIdx.x * 256 + threadIdx.x;
    int l = blockIdx.y;
    float4 wv = ((const float4*)cw)[d];
    const float* xp = g_xz + d;
    float acc = wv.w * xp[(size_t)l * DXZ];
    if (l >= 1) acc += wv.z * xp[(size_t)(l-1) * DXZ];
    if (l >= 2) acc += wv.y * xp[(size_t)(l-2) * DXZ];
    if (l >= 3) acc += wv.x * xp[(size_t)(l-3) * DXZ];
    g_xa[(size_t)l * DI + d] = silu_f(acc);
}

// ---------------- 4) proj GEMM split-K=8 ----------------
__global__ void proj_gemm(const float* __restrict__ A, const float* __restrict__ B){
    __shared__ float As[16][64];
    __shared__ float Bs[16][64];
    int tid = threadIdx.x;
    int by  = blockIdx.x;
    int ks  = blockIdx.y;
    int k0b = ks * 160;

    int arow = tid >> 2;
    int acol = (tid & 3) * 4;
    const float* Ap = A + (size_t)(by*64 + arow) * DI + k0b + acol;

    float acc[4][4];
    #pragma unroll
    for (int i = 0; i < 4; i++)
        #pragma unroll
        for (int j = 0; j < 4; j++) acc[i][j] = 0.f;

    int ty = tid >> 4, tx = tid & 15;

    for (int k0 = 0; k0 < 160; k0 += 16){
        float4 av = *(const float4*)Ap;
        float bl[4];
        #pragma unroll
        for (int q = 0; q < 4; q++){
            int e = tid*4 + q;
            int rr = e >> 6, c = e & 63;
            bl[q] = (c < NPROJ) ? B[(size_t)(k0b + k0 + rr) * NPROJ + c] : 0.f;
        }
        __syncthreads();
        As[acol+0][arow] = av.x;
        As[acol+1][arow] = av.y;
        As[acol+2][arow] = av.z;
        As[acol+3][arow] = av.w;
        #pragma unroll
        for (int q = 0; q < 4; q++){
            int e = tid*4 + q;
            Bs[e >> 6][e & 63] = bl[q];
        }
        __syncthreads();
        #pragma unroll
        for (int k = 0; k < 16; k++){
            float ar[4], br[4];
            #pragma unroll
            for (int i = 0; i < 4; i++) ar[i] = As[k][ty*4 + i];
            #pragma unroll
            for (int j = 0; j < 4; j++) br[j] = Bs[k][tx*4 + j];
            #pragma unroll
            for (int i = 0; i < 4; i++)
                #pragma unroll
                for (int j = 0; j < 4; j++)
                    acc[i][j] = fmaf(ar[i], br[j], acc[i][j]);
        }
        __syncthreads();
        Ap += 16;
    }
    float* Cp = g_pp + (size_t)ks * PSLICE;
    #pragma unroll
    for (int i = 0; i < 4; i++){
        int row = by*64 + ty*4 + i;
        #pragma unroll
        for (int j = 0; j < 4; j++){
            int col = tx*4 + j;
            if (col < NPROJ) Cp[(size_t)row * NPROJ + col] = acc[i][j];
        }
    }
}

__global__ void proj_reduce(){
    int i = blockIdx.x * 256 + threadIdx.x;
    if (i < PSLICE){
        float a = 0.f;
        #pragma unroll
        for (int k = 0; k < 8; k++) a += g_pp[(size_t)k * PSLICE + i];
        g_proj[i] = a;
    }
}

// ---------------- 5) dt ----------------
__global__ void dt_kernel(const float* __restrict__ Wdt, const float* __restrict__ bias){
    __shared__ float pr[8][RANK];
    int t  = threadIdx.x;
    int d  = blockIdx.x * 256 + t;
    int l0 = blockIdx.y * 8;
    if (t < 8 * RANK)
        pr[t / RANK][t % RANK] = g_proj[(size_t)(l0 + t / RANK) * NPROJ + (t % RANK)];
    __syncthreads();

    float acc[8];
    #pragma unroll
    for (int j = 0; j < 8; j++) acc[j] = 0.f;
    for (int k = 0; k < RANK; k++){
        float wv = Wdt[(size_t)k * DI + d];
        #pragma unroll
        for (int j = 0; j < 8; j++) acc[j] = fmaf(pr[j][k], wv, acc[j]);
    }
    float bb = bias[d];
    #pragma unroll
    for (int j = 0; j < 8; j++){
        float v = acc[j] + bb;
        float sp = (v > 20.f) ? v : log1pf(__expf(v));
        g_dt[(size_t)(l0 + j) * DI + d] = sp;
    }
}

// ---------------- 6) chunked parallel scan ----------------
__global__ void __launch_bounds__(256)
scan_phaseA(const float* __restrict__ A_log){
    int t = threadIdx.x;
    int d = blockIdx.x * 256 + t;
    int g = blockIdx.y;

    float Ac[8];
    #pragma unroll
    for (int s = 0; s < 8; s++) Ac[s] = -__expf(A_log[d*8 + s]);
    bool fast = true;
    #pragma unroll
    for (int s = 0; s < 8; s++){
        float r = Ac[s] / Ac[0];
        if (fabsf(r - (float)(s+1)) > 1e-3f) fast = false;
    }

    float h[8];
    #pragma unroll
    for (int s = 0; s < 8; s++) h[s] = 0.f;
    float Etot = 1.f;

    const float* dtp = g_dt   + (size_t)(g*CLEN) * DI + d;
    const float* xap = g_xa   + (size_t)(g*CLEN) * DI + d;
    const float* bp  = g_proj + (size_t)(g*CLEN) * NPROJ + RANK;

    if (fast){
        for (int l = 0; l < CLEN; l++){
            float dtv = *dtp, xav = *xap;
            float e1 = __expf(dtv * Ac[0]);
            float db = dtv * xav;
            Etot *= e1;
            float p = 1.f;
            #pragma unroll
            for (int s = 0; s < 8; s++){
                p *= e1;
                h[s] = fmaf(p, h[s], db * __ldg(bp + s));
            }
            dtp += DI; xap += DI; bp += NPROJ;
        }
        size_t base = (size_t)g * DS + d*8;
        float P = 1.f;
        #pragma unroll
        for (int s = 0; s < 8; s++){
            P *= Etot;
            g_cP[base + s] = P;
            g_cH[base + s] = h[s];
        }
    } else {
        float Ps[8];
        #pragma unroll
        for (int s = 0; s < 8; s++) Ps[s] = 1.f;
        for (int l = 0; l < CLEN; l++){
            float dtv = *dtp, xav = *xap;
            float db = dtv * xav;
            #pragma unroll
            for (int s = 0; s < 8; s++){
                float dA = __expf(dtv * Ac[s]);
                Ps[s] *= dA;
                h[s] = fmaf(dA, h[s], db * __ldg(bp + s));
            }
            dtp += DI; xap += DI; bp += NPROJ;
        }
        size_t base = (size_t)g * DS + d*8;
        #pragma unroll
        for (int s = 0; s < 8; s++){
            g_cP[base + s] = Ps[s];
            g_cH[base + s] = h[s];
        }
    }
}

__global__ void scan_phaseB(){
    int idx = blockIdx.x * 256 + threadIdx.x;
    float h = 0.f;
    for (int g = 0; g < NCHUNK; g++){
        size_t o = (size_t)g * DS + idx;
        g_h0[o] = h;
        h = fmaf(g_cP[o], h, g_cH[o]);
    }
}

__global__ void __launch_bounds__(256)
scan_phaseC(const float* __restrict__ A_log, const float* __restrict__ Dp){
    int t = threadIdx.x;
    int d = blockIdx.x * 256 + t;
    int g = blockIdx.y;

    float Ac[8];
    #pragma unroll
    for (int s = 0; s < 8; s++) Ac[s] = -__expf(A_log[d*8 + s]);
    bool fast = true;
    #pragma unroll
    for (int s = 0; s < 8; s++){
        float r = Ac[s] / Ac[0];
        if (fabsf(r - (float)(s+1)) > 1e-3f) fast = false;
    }

    float h[8];
    size_t hb = (size_t)g * DS + d*8;
    #pragma unroll
    for (int s = 0; s < 8; s++) h[s] = g_h0[hb + s];
    float Dval = Dp[d];

    const float* dtp = g_dt   + (size_t)(g*CLEN) * DI + d;
    const float* xap = g_xa   + (size_t)(g*CLEN) * DI + d;
    const float* zp  = g_xz   + (size_t)(g*CLEN) * DXZ + DI + d;
    const float* bp  = g_proj + (size_t)(g*CLEN) * NPROJ + RANK;
    size_t yoff = (size_t)(g*CLEN) * DI + d;

    if (fast){
        for (int l = 0; l < CLEN; l++){
            float dtv = *dtp, xav = *xap;
            float e1 = __expf(dtv * Ac[0]);
            float db = dtv * xav;
            float p = 1.f, yv = 0.f;
            #pragma unroll
            for (int s = 0; s < 8; s++){
                p *= e1;
                h[s] = fmaf(p, h[s], db * __ldg(bp + s));
                yv = fmaf(h[s], __ldg(bp + 8 + s), yv);
            }
            float val = (yv + xav * Dval) * silu_f(*zp);
            split_store(val, g_a2hi, g_a2lo, yoff);
            dtp += DI; xap += DI; zp += DXZ; bp += NPROJ; yoff += DI;
        }
    } else {
        for (int l = 0; l < CLEN; l++){
            float dtv = *dtp, xav = *xap;
            float db = dtv * xav;
            float yv = 0.f;
            #pragma unroll
            for (int s = 0; s < 8; s++){
                float dA = __expf(dtv * Ac[s]);
                h[s] = fmaf(dA, h[s], db * __ldg(bp + s));
                yv = fmaf(h[s], __ldg(bp + 8 + s), yv);
            }
            float val = (yv + xav * Dval) * silu_f(*zp);
            split_store(val, g_a2hi, g_a2lo, yoff);
            dtp += DI; xap += DI; zp += DXZ; bp += NPROJ; yoff += DI;
        }
    }
}

// ---------------- launch ----------------
extern "C" void kernel_launch(void* const* d_in, const int* in_sizes, int n_in,
                              void* d_out, int out_size){
    const float* x       = (const float*)d_in[0];
    const float* y       = (const float*)d_in[1];
    const float* ln_g    = (const float*)d_in[2];
    const float* ln_b    = (const float*)d_in[3];
    const float* W_in    = (const float*)d_in[4];
    const float* conv_w  = (const float*)d_in[5];
    const float* W_xproj = (const float*)d_in[6];
    const float* W_dt    = (const float*)d_in[7];
    const float* dt_bias = (const float*)d_in[8];
    const float* A_log   = (const float*)d_in[9];
    const float* Dp      = (const float*)d_in[10];
    const float* W_out   = (const float*)d_in[11];
    float* out = (float*)d_out;

    cudaFuncSetAttribute(gemm_wmma<0>, cudaFuncAttributeMaxDynamicSharedMemorySize, GEMM_SMEM);
    cudaFuncSetAttribute(gemm_wmma<1>, cudaFuncAttributeMaxDynamicSharedMemorySize, GEMM_SMEM);

    float *xz_p, *xa_p;
    __nv_bfloat16 *a1h, *a1l, *b1h, *b1l, *a2h, *a2l, *b2h, *b2l;
    cudaGetSymbolAddress((void**)&xz_p, g_xz);
    cudaGetSymbolAddress((void**)&xa_p, g_xa);
    cudaGetSymbolAddress((void**)&a1h, g_a1hi);  cudaGetSymbolAddress((void**)&a1l, g_a1lo);
    cudaGetSymbolAddress((void**)&b1h, g_b1hi);  cudaGetSymbolAddress((void**)&b1l, g_b1lo);
    cudaGetSymbolAddress((void**)&a2h, g_a2hi);  cudaGetSymbolAddress((void**)&a2l, g_a2lo);
    cudaGetSymbolAddress((void**)&b2h, g_b2hi);  cudaGetSymbolAddress((void**)&b2l, g_b2lo);

    // weight transposes + bf16 split
    transpose_split<<<dim3(DXZ/32, CDIM/32), dim3(32,8)>>>(W_in,  b1h, b1l, CDIM, DXZ);
    transpose_split<<<dim3(CDIM/32, DI/32),  dim3(32,8)>>>(W_out, b2h, b2l, DI,   CDIM);

    // 1) gather + layernorm -> a1 (bf16 hi/lo)
    ln_kernel<<<LSEQ, 256>>>(x, y, ln_g, ln_b);

    // 2) xz = ln(seq) @ W_in   (tensor cores, bf16 3-term)
    gemm_wmma<0><<<dim3(DXZ/128, LSEQ/128), 256, GEMM_SMEM>>>(
        a1h, a1l, b1h, b1l, xz_p, CDIM, DXZ, nullptr, nullptr, nullptr);

    // 3) xa = silu(causal_dwconv(xp))
    conv_silu_kernel<<<dim3(DI/256, LSEQ), 256>>>(conv_w);

    // 4) proj = xa @ W_xproj (split-K=8)
    proj_gemm<<<dim3(LSEQ/64, 8), 256>>>(xa_p, W_xproj);
    proj_reduce<<<(PSLICE + 255)/256, 256>>>();

    // 5) dt
    dt_kernel<<<dim3(DI/256, LSEQ/8), 256>>>(W_dt, dt_bias);

    // 6) chunked parallel scan + gating -> a2 (bf16 hi/lo)
    scan_phaseA<<<dim3(DI/256, NCHUNK), 256>>>(A_log);
    scan_phaseB<<<DS/256, 256>>>();
    scan_phaseC<<<dim3(DI/256, NCHUNK), 256>>>(A_log, Dp);

    // 7) out = yo @ W_out + seq  (tensor cores, fused residual + scatter)
    gemm_wmma<1><<<dim3(CDIM/128, LSEQ/128), 256, GEMM_SMEM>>>(
        a2h, a2l, b2h, b2l, nullptr, DI, CDIM, x, y, out);
}

// round 7
// speedup vs baseline: 10.0304x; 1.1362x over previous
#include <cuda_runtime.h>
#include <cuda_bf16.h>
#include <mma.h>
#include <cstdint>

using namespace nvcuda;

#define LSEQ 4608
#define CDIM 640
#define DI   1280
#define DXZ  2560
#define NPROJ 56
#define RANK  40
#define PLANE 2304          // 48*48
#define XFSZ  (640*2304)
#define PSLICE (LSEQ*NPROJ)
#define NCHUNK 72
#define CLEN   64
#define DS     (DI*8)

// ---------------- scratch ----------------
__device__ float g_xz  [LSEQ*DXZ];
__device__ float g_xa  [LSEQ*DI];
__device__ float g_proj[LSEQ*NPROJ];
__device__ float g_pp  [8*PSLICE];
__device__ float g_dt  [LSEQ*DI];
__device__ float g_cP  [NCHUNK*DS];
__device__ float g_cH  [NCHUNK*DS];
__device__ float g_h0  [NCHUNK*DS];
// bf16 hi/lo operands for tensor-core GEMMs (16B-aligned for cp.async)
__device__ __align__(256) __nv_bfloat16 g_a1hi[LSEQ*CDIM], g_a1lo[LSEQ*CDIM]; // ln(seq)
__device__ __align__(256) __nv_bfloat16 g_b1hi[DXZ*CDIM],  g_b1lo[DXZ*CDIM];  // W_in^T  [2560,640]
__device__ __align__(256) __nv_bfloat16 g_a2hi[LSEQ*DI],   g_a2lo[LSEQ*DI];   // yo
__device__ __align__(256) __nv_bfloat16 g_b2hi[CDIM*DI],   g_b2lo[CDIM*DI];   // W_out^T [640,1280]

// ---------------- helpers ----------------
#define CP_ASYNC16(dst, src) \
    asm volatile("cp.async.cg.shared.global [%0], [%1], 16;" :: "r"(dst), "l"(src) : "memory")
#define CP_COMMIT() asm volatile("cp.async.commit_group;" ::: "memory")
#define CP_WAIT(n)  asm volatile("cp.async.wait_group %0;" :: "n"(n) : "memory")

__device__ __forceinline__ uint32_t smem_u32(const void* p){
    uint32_t a;
    asm("{ .reg .u64 t; cvta.to.shared.u64 t, %1; cvt.u32.u64 %0, t; }" : "=r"(a) : "l"(p));
    return a;
}
__device__ __forceinline__ float silu_f(float v){ return v / (1.0f + __expf(-v)); }
__device__ __forceinline__ void split_store(float v, __nv_bfloat16* hi, __nv_bfloat16* lo, size_t off){
    __nv_bfloat16 h = __float2bfloat16(v);
    hi[off] = h;
    lo[off] = __float2bfloat16(v - __bfloat162float(h));
}

// ---------------- 1) gather + layernorm -> bf16 hi/lo ----------------
__global__ void ln_kernel(const float* __restrict__ x, const float* __restrict__ yy,
                          const float* __restrict__ g, const float* __restrict__ b){
    int l  = blockIdx.x;
    int h  = l / 96;
    int w2 = l - h * 96;
    const float* src = (w2 < 48) ? (x + h*48 + w2) : (yy + h*48 + (w2-48));
    int t = threadIdx.x;   // 256

    float v0 = src[(size_t)t       * PLANE];
    float v1 = src[(size_t)(t+256) * PLANE];
    float v2 = (t < 128) ? src[(size_t)(t+512) * PLANE] : 0.f;

    float s  = v0 + v1 + v2;
    float s2 = v0*v0 + v1*v1 + v2*v2;
    #pragma unroll
    for (int o = 16; o > 0; o >>= 1){
        s  += __shfl_xor_sync(0xffffffffu, s , o);
        s2 += __shfl_xor_sync(0xffffffffu, s2, o);
    }
    __shared__ float rs[8], rs2[8];
    int wid = t >> 5, lid = t & 31;
    if (lid == 0){ rs[wid] = s; rs2[wid] = s2; }
    __syncthreads();
    if (t == 0){
        float a = 0.f, a2 = 0.f;
        #pragma unroll
        for (int i = 0; i < 8; i++){ a += rs[i]; a2 += rs2[i]; }
        rs[0] = a; rs2[0] = a2;
    }
    __syncthreads();
    float mean = rs[0]  * (1.f/640.f);
    float var  = rs2[0] * (1.f/640.f) - mean*mean;
    float inv  = rsqrtf(var + 1e-5f);

    size_t base = (size_t)l * CDIM;
    float o0 = (v0 - mean) * inv * g[t]       + b[t];
    float o1 = (v1 - mean) * inv * g[t + 256] + b[t + 256];
    split_store(o0, g_a1hi, g_a1lo, base + t);
    split_store(o1, g_a1hi, g_a1lo, base + t + 256);
    if (t < 128){
        float o2 = (v2 - mean) * inv * g[t + 512] + b[t + 512];
        split_store(o2, g_a1hi, g_a1lo, base + t + 512);
    }
}

// ---------------- weight transpose + bf16 split: W[K,N] -> Wt[n*K+k] ----------------
__global__ void transpose_split(const float* __restrict__ W,
                                __nv_bfloat16* __restrict__ hi, __nv_bfloat16* __restrict__ lo,
                                int K, int N){
    __shared__ float tile[32][33];
    int n0 = blockIdx.x * 32, k0 = blockIdx.y * 32;
    int tx = threadIdx.x, ty = threadIdx.y;   // (32, 8)
    #pragma unroll
    for (int i = 0; i < 4; i++)
        tile[ty + 8*i][tx] = W[(size_t)(k0 + ty + 8*i) * N + n0 + tx];
    __syncthreads();
    #pragma unroll
    for (int i = 0; i < 4; i++){
        float v = tile[tx][ty + 8*i];
        size_t o = (size_t)(n0 + ty + 8*i) * K + k0 + tx;
        __nv_bfloat16 h = __float2bfloat16(v);
        hi[o] = h;
        lo[o] = __float2bfloat16(v - __bfloat162float(h));
    }
}

// ---------------- wmma bf16-split GEMM: C[M,Nc] = A[M,K] @ B[Nc,K]^T ----------------
// 3 terms: Ahi*Bhi + Alo*Bhi + Ahi*Blo, fp32 accumulators.
// Block tile 128x128, warps 4x2 (32x64 each), BK=32, cp.async double buffer.
// LDS_E=40 (80B rows): 8 tiles x 10240B = 80KB -> 2 CTAs/SM with 128-reg cap.
#define LDS_E 40                         // bf16 smem row stride (80B, mult of 16B)
#define STG_LD 68                        // fp32 staging ldm, multiple of 4
#define TILE_BYTES (128*LDS_E*2)         // 10240
#define GEMM_SMEM  (8*TILE_BYTES)        // 81920

template<int MODE>
__global__ void __launch_bounds__(256, 2)
gemm_wmma(const __nv_bfloat16* __restrict__ Ahi, const __nv_bfloat16* __restrict__ Alo,
          const __nv_bfloat16* __restrict__ Bhi, const __nv_bfloat16* __restrict__ Blo,
          float* __restrict__ C, int K, int Nc,
          const float* __restrict__ rx, const float* __restrict__ ry,
          float* __restrict__ outp){
    extern __shared__ __align__(32) char smem[];
    uint32_t sbase = smem_u32(smem);
    int tid = threadIdx.x;
    int wid = tid >> 5, lane = tid & 31;
    int wr = wid & 3, wc = wid >> 2;          // 4 x 2 warp grid
    int n0 = blockIdx.x * 128, m0 = blockIdx.y * 128;

    const char* srcs[4] = {
        (const char*)(Ahi + (size_t)m0 * K), (const char*)(Alo + (size_t)m0 * K),
        (const char*)(Bhi + (size_t)n0 * K), (const char*)(Blo + (size_t)n0 * K) };
    int rowbytes = K * 2;
    int nstage = K / 32;

    wmma::fragment<wmma::accumulator, 16, 16, 16, float> acc[2][4];
    #pragma unroll
    for (int i = 0; i < 2; i++)
        #pragma unroll
        for (int j = 0; j < 4; j++) wmma::fill_fragment(acc[i][j], 0.f);

    auto load_stage = [&](int st, int k0bytes){
        #pragma unroll
        for (int tl = 0; tl < 4; tl++){
            const char* bp = srcs[tl] + k0bytes;
            uint32_t tb = sbase + (uint32_t)((st*4 + tl) * TILE_BYTES);
            #pragma unroll
            for (int j = 0; j < 2; j++){
                int cidx = tid + j*256;          // 0..511
                int row = cidx >> 2, c = cidx & 3;
                CP_ASYNC16(tb + (uint32_t)(row*(LDS_E*2) + c*16),
                           bp + (size_t)row * rowbytes + c*16);
            }
        }
        CP_COMMIT();
    };

    load_stage(0, 0);

    for (int t = 0; t < nstage; t++){
        int s = t & 1;
        if (t + 1 < nstage){
            load_stage(s ^ 1, (t+1)*64);
            CP_WAIT(1);
        } else {
            CP_WAIT(0);
        }
        __syncthreads();

        const __nv_bfloat16* As_h = (const __nv_bfloat16*)(smem + (s*4 + 0)*TILE_BYTES);
        const __nv_bfloat16* As_l = (const __nv_bfloat16*)(smem + (s*4 + 1)*TILE_BYTES);
        const __nv_bfloat16* Bs_h = (const __nv_bfloat16*)(smem + (s*4 + 2)*TILE_BYTES);
        const __nv_bfloat16* Bs_l = (const __nv_bfloat16*)(smem + (s*4 + 3)*TILE_BYTES);

        #pragma unroll
        for (int kf = 0; kf < 2; kf++){
            wmma::fragment<wmma::matrix_a, 16, 16, 16, __nv_bfloat16, wmma::row_major> ah[2], al[2];
            #pragma unroll
            for (int i = 0; i < 2; i++){
                int r = wr*32 + i*16;
                wmma::load_matrix_sync(ah[i], As_h + r*LDS_E + kf*16, LDS_E);
                wmma::load_matrix_sync(al[i], As_l + r*LDS_E + kf*16, LDS_E);
            }
            #pragma unroll
            for (int j = 0; j < 4; j++){
                wmma::fragment<wmma::matrix_b, 16, 16, 16, __nv_bfloat16, wmma::col_major> bh, bl;
                int c = wc*64 + j*16;
                wmma::load_matrix_sync(bh, Bs_h + c*LDS_E + kf*16, LDS_E);
                wmma::load_matrix_sync(bl, Bs_l + c*LDS_E + kf*16, LDS_E);
                #pragma unroll
                for (int i = 0; i < 2; i++){
                    wmma::mma_sync(acc[i][j], ah[i], bh, acc[i][j]);
                    wmma::mma_sync(acc[i][j], al[i], bh, acc[i][j]);
                    wmma::mma_sync(acc[i][j], ah[i], bl, acc[i][j]);
                }
            }
        }
        __syncthreads();
    }

    if (MODE == 0){
        #pragma unroll
        for (int i = 0; i < 2; i++)
            #pragma unroll
            for (int j = 0; j < 4; j++){
                float* cp = C + (size_t)(m0 + wr*32 + i*16) * Nc + n0 + wc*64 + j*16;
                wmma::store_matrix_sync(cp, acc[i][j], Nc, wmma::mem_row_major);
            }
    } else {
        // stage 32x64 warp tile into padded smem, then coalesced scatter
        float* stg = (float*)smem + (size_t)wid * (32*STG_LD);
        #pragma unroll
        for (int i = 0; i < 2; i++)
            #pragma unroll
            for (int j = 0; j < 4; j++)
                wmma::store_matrix_sync(stg + i*16*STG_LD + j*16, acc[i][j], STG_LD,
                                        wmma::mem_row_major);
        __syncwarp();

        int row = m0 + wr*32 + lane;          // lane = local row
        int h   = row / 96;
        int w2  = row - h*96;
        bool isx = (w2 < 48);
        int  w   = isx ? w2 : (w2 - 48);
        const float* rsrc = (isx ? rx : ry) + h*48 + w;
        float* od = outp + (isx ? 0 : XFSZ) + h*48 + w;
        #pragma unroll 8
        for (int j = 0; j < 64; j++){
            int col = n0 + wc*64 + j;
            od[(size_t)col * PLANE] = stg[lane*STG_LD + j] + rsrc[(size_t)col * PLANE];
        }
    }
}

// ---------------- 3) causal depthwise conv (K=4) + SiLU ----------------
__global__ void conv_silu_kernel(const float* __restrict__ cw){
    int d = blockIdx.x * 256 + threadIdx.x;
    int l = blockIdx.y;
    float4 wv = ((const float4*)cw)[d];
    const float* xp = g_xz + d;
    float acc = wv.w * xp[(size_t)l * DXZ];
    if (l >= 1) acc += wv.z * xp[(size_t)(l-1) * DXZ];
    if (l >= 2) acc += wv.y * xp[(size_t)(l-2) * DXZ];
    if (l >= 3) acc += wv.x * xp[(size_t)(l-3) * DXZ];
    g_xa[(size_t)l * DI + d] = silu_f(acc);
}

// ---------------- 4) proj GEMM split-K=8 ----------------
__global__ void proj_gemm(const float* __restrict__ A, const float* __restrict__ B){
    __shared__ float As[16][64];
    __shared__ float Bs[16][64];
    int tid = threadIdx.x;
    int by  = blockIdx.x;
    int ks  = blockIdx.y;
    int k0b = ks * 160;

    int arow = tid >> 2;
    int acol = (tid & 3) * 4;
    const float* Ap = A + (size_t)(by*64 + arow) * DI + k0b + acol;

    float acc[4][4];
    #pragma unroll
    for (int i = 0; i < 4; i++)
        #pragma unroll
        for (int j = 0; j < 4; j++) acc[i][j] = 0.f;

    int ty = tid >> 4, tx = tid & 15;

    for (int k0 = 0; k0 < 160; k0 += 16){
        float4 av = *(const float4*)Ap;
        float bl[4];
        #pragma unroll
        for (int q = 0; q < 4; q++){
            int e = tid*4 + q;
            int rr = e >> 6, c = e & 63;
            bl[q] = (c < NPROJ) ? B[(size_t)(k0b + k0 + rr) * NPROJ + c] : 0.f;
        }
        __syncthreads();
        As[acol+0][arow] = av.x;
        As[acol+1][arow] = av.y;
        As[acol+2][arow] = av.z;
        As[acol+3][arow] = av.w;
        #pragma unroll
        for (int q = 0; q < 4; q++){
            int e = tid*4 + q;
            Bs[e >> 6][e & 63] = bl[q];
        }
        __syncthreads();
        #pragma unroll
        for (int k = 0; k < 16; k++){
            float ar[4], br[4];
            #pragma unroll
            for (int i = 0; i < 4; i++) ar[i] = As[k][ty*4 + i];
            #pragma unroll
            for (int j = 0; j < 4; j++) br[j] = Bs[k][tx*4 + j];
            #pragma unroll
            for (int i = 0; i < 4; i++)
                #pragma unroll
                for (int j = 0; j < 4; j++)
                    acc[i][j] = fmaf(ar[i], br[j], acc[i][j]);
        }
        __syncthreads();
        Ap += 16;
    }
    float* Cp = g_pp + (size_t)ks * PSLICE;
    #pragma unroll
    for (int i = 0; i < 4; i++){
        int row = by*64 + ty*4 + i;
        #pragma unroll
        for (int j = 0; j < 4; j++){
            int col = tx*4 + j;
            if (col < NPROJ) Cp[(size_t)row * NPROJ + col] = acc[i][j];
        }
    }
}

__global__ void proj_reduce(){
    int i = blockIdx.x * 256 + threadIdx.x;
    if (i < PSLICE){
        float a = 0.f;
        #pragma unroll
        for (int k = 0; k < 8; k++) a += g_pp[(size_t)k * PSLICE + i];
        g_proj[i] = a;
    }
}

// ---------------- 5) dt ----------------
__global__ void dt_kernel(const float* __restrict__ Wdt, const float* __restrict__ bias){
    __shared__ float pr[8][RANK];
    int t  = threadIdx.x;
    int d  = blockIdx.x * 256 + t;
    int l0 = blockIdx.y * 8;
    if (t < 8 * RANK)
        pr[t / RANK][t % RANK] = g_proj[(size_t)(l0 + t / RANK) * NPROJ + (t % RANK)];
    __syncthreads();

    float acc[8];
    #pragma unroll
    for (int j = 0; j < 8; j++) acc[j] = 0.f;
    for (int k = 0; k < RANK; k++){
        float wv = Wdt[(size_t)k * DI + d];
        #pragma unroll
        for (int j = 0; j < 8; j++) acc[j] = fmaf(pr[j][k], wv, acc[j]);
    }
    float bb = bias[d];
    #pragma unroll
    for (int j = 0; j < 8; j++){
        float v = acc[j] + bb;
        float sp = (v > 20.f) ? v : log1pf(__expf(v));
        g_dt[(size_t)(l0 + j) * DI + d] = sp;
    }
}

// ---------------- 6) chunked parallel scan ----------------
__global__ void __launch_bounds__(256)
scan_phaseA(const float* __restrict__ A_log){
    int t = threadIdx.x;
    int d = blockIdx.x * 256 + t;
    int g = blockIdx.y;

    float Ac[8];
    #pragma unroll
    for (int s = 0; s < 8; s++) Ac[s] = -__expf(A_log[d*8 + s]);
    bool fast = true;
    #pragma unroll
    for (int s = 0; s < 8; s++){
        float r = Ac[s] / Ac[0];
        if (fabsf(r - (float)(s+1)) > 1e-3f) fast = false;
    }

    float h[8];
    #pragma unroll
    for (int s = 0; s < 8; s++) h[s] = 0.f;
    float Etot = 1.f;

    const float* dtp = g_dt   + (size_t)(g*CLEN) * DI + d;
    const float* xap = g_xa   + (size_t)(g*CLEN) * DI + d;
    const float* bp  = g_proj + (size_t)(g*CLEN) * NPROJ + RANK;

    if (fast){
        for (int l = 0; l < CLEN; l++){
            float dtv = *dtp, xav = *xap;
            float e1 = __expf(dtv * Ac[0]);
            float db = dtv * xav;
            Etot *= e1;
            float p = 1.f;
            #pragma unroll
            for (int s = 0; s < 8; s++){
                p *= e1;
                h[s] = fmaf(p, h[s], db * __ldg(bp + s));
            }
            dtp += DI; xap += DI; bp += NPROJ;
        }
        size_t base = (size_t)g * DS + d*8;
        float P = 1.f;
        #pragma unroll
        for (int s = 0; s < 8; s++){
            P *= Etot;
            g_cP[base + s] = P;
            g_cH[base + s] = h[s];
        }
    } else {
        float Ps[8];
        #pragma unroll
        for (int s = 0; s < 8; s++) Ps[s] = 1.f;
        for (int l = 0; l < CLEN; l++){
            float dtv = *dtp, xav = *xap;
            float db = dtv * xav;
            #pragma unroll
            for (int s = 0; s < 8; s++){
                float dA = __expf(dtv * Ac[s]);
                Ps[s] *= dA;
                h[s] = fmaf(dA, h[s], db * __ldg(bp + s));
            }
            dtp += DI; xap += DI; bp += NPROJ;
        }
        size_t base = (size_t)g * DS + d*8;
        #pragma unroll
        for (int s = 0; s < 8; s++){
            g_cP[base + s] = Ps[s];
            g_cH[base + s] = h[s];
        }
    }
}

__global__ void scan_phaseB(){
    int idx = blockIdx.x * 256 + threadIdx.x;
    float h = 0.f;
    for (int g = 0; g < NCHUNK; g++){
        size_t o = (size_t)g * DS + idx;
        g_h0[o] = h;
        h = fmaf(g_cP[o], h, g_cH[o]);
    }
}

__global__ void __launch_bounds__(256)
scan_phaseC(const float* __restrict__ A_log, const float* __restrict__ Dp){
    int t = threadIdx.x;
    int d = blockIdx.x * 256 + t;
    int g = blockIdx.y;

    float Ac[8];
    #pragma unroll
    for (int s = 0; s < 8; s++) Ac[s] = -__expf(A_log[d*8 + s]);
    bool fast = true;
    #pragma unroll
    for (int s = 0; s < 8; s++){
        float r = Ac[s] / Ac[0];
        if (fabsf(r - (float)(s+1)) > 1e-3f) fast = false;
    }

    float h[8];
    size_t hb = (size_t)g * DS + d*8;
    #pragma unroll
    for (int s = 0; s < 8; s++) h[s] = g_h0[hb + s];
    float Dval = Dp[d];

    const float* dtp = g_dt   + (size_t)(g*CLEN) * DI + d;
    const float* xap = g_xa   + (size_t)(g*CLEN) * DI + d;
    const float* zp  = g_xz   + (size_t)(g*CLEN) * DXZ + DI + d;
    const float* bp  = g_proj + (size_t)(g*CLEN) * NPROJ + RANK;
    size_t yoff = (size_t)(g*CLEN) * DI + d;

    if (fast){
        for (int l = 0; l < CLEN; l++){
            float dtv = *dtp, xav = *xap;
            float e1 = __expf(dtv * Ac[0]);
            float db = dtv * xav;
            float p = 1.f, yv = 0.f;
            #pragma unroll
            for (int s = 0; s < 8; s++){
                p *= e1;
                h[s] = fmaf(p, h[s], db * __ldg(bp + s));
                yv = fmaf(h[s], __ldg(bp + 8 + s), yv);
            }
            float val = (yv + xav * Dval) * silu_f(*zp);
            split_store(val, g_a2hi, g_a2lo, yoff);
            dtp += DI; xap += DI; zp += DXZ; bp += NPROJ; yoff += DI;
        }
    } else {
        for (int l = 0; l < CLEN; l++){
            float dtv = *dtp, xav = *xap;
            float db = dtv * xav;
            float yv = 0.f;
            #pragma unroll
            for (int s = 0; s < 8; s++){
                float dA = __expf(dtv * Ac[s]);
                h[s] = fmaf(dA, h[s], db * __ldg(bp + s));
                yv = fmaf(h[s], __ldg(bp + 8 + s), yv);
            }
            float val = (yv + xav * Dval) * silu_f(*zp);
            split_store(val, g_a2hi, g_a2lo, yoff);
            dtp += DI; xap += DI; zp += DXZ; bp += NPROJ; yoff += DI;
        }
    }
}

// ---------------- launch ----------------
extern "C" void kernel_launch(void* const* d_in, const int* in_sizes, int n_in,
                              void* d_out, int out_size){
    const float* x       = (const float*)d_in[0];
    const float* y       = (const float*)d_in[1];
    const float* ln_g    = (const float*)d_in[2];
    const float* ln_b    = (const float*)d_in[3];
    const float* W_in    = (const float*)d_in[4];
    const float* conv_w  = (const float*)d_in[5];
    const float* W_xproj = (const float*)d_in[6];
    const float* W_dt    = (const float*)d_in[7];
    const float* dt_bias = (const float*)d_in[8];
    const float* A_log   = (const float*)d_in[9];
    const float* Dp      = (const float*)d_in[10];
    const float* W_out   = (const float*)d_in[11];
    float* out = (float*)d_out;

    cudaFuncSetAttribute(gemm_wmma<0>, cudaFuncAttributeMaxDynamicSharedMemorySize, GEMM_SMEM);
    cudaFuncSetAttribute(gemm_wmma<1>, cudaFuncAttributeMaxDynamicSharedMemorySize, GEMM_SMEM);

    float *xz_p, *xa_p;
    __nv_bfloat16 *a1h, *a1l, *b1h, *b1l, *a2h, *a2l, *b2h, *b2l;
    cudaGetSymbolAddress((void**)&xz_p, g_xz);
    cudaGetSymbolAddress((void**)&xa_p, g_xa);
    cudaGetSymbolAddress((void**)&a1h, g_a1hi);  cudaGetSymbolAddress((void**)&a1l, g_a1lo);
    cudaGetSymbolAddress((void**)&b1h, g_b1hi);  cudaGetSymbolAddress((void**)&b1l, g_b1lo);
    cudaGetSymbolAddress((void**)&a2h, g_a2hi);  cudaGetSymbolAddress((void**)&a2l, g_a2lo);
    cudaGetSymbolAddress((void**)&b2h, g_b2hi);  cudaGetSymbolAddress((void**)&b2l, g_b2lo);

    // weight transposes + bf16 split
    transpose_split<<<dim3(DXZ/32, CDIM/32), dim3(32,8)>>>(W_in,  b1h, b1l, CDIM, DXZ);
    transpose_split<<<dim3(CDIM/32, DI/32),  dim3(32,8)>>>(W_out, b2h, b2l, DI,   CDIM);

    // 1) gather + layernorm -> a1 (bf16 hi/lo)
    ln_kernel<<<LSEQ, 256>>>(x, y, ln_g, ln_b);

    // 2) xz = ln(seq) @ W_in   (tensor cores, bf16 3-term)
    gemm_wmma<0><<<dim3(DXZ/128, LSEQ/128), 256, GEMM_SMEM>>>(
        a1h, a1l, b1h, b1l, xz_p, CDIM, DXZ, nullptr, nullptr, nullptr);

    // 3) xa = silu(causal_dwconv(xp))
    conv_silu_kernel<<<dim3(DI/256, LSEQ), 256>>>(conv_w);

    // 4) proj = xa @ W_xproj (split-K=8)
    proj_gemm<<<dim3(LSEQ/64, 8), 256>>>(xa_p, W_xproj);
    proj_reduce<<<(PSLICE + 255)/256, 256>>>();

    // 5) dt
    dt_kernel<<<dim3(DI/256, LSEQ/8), 256>>>(W_dt, dt_bias);

    // 6) chunked parallel scan + gating -> a2 (bf16 hi/lo)
    scan_phaseA<<<dim3(DI/256, NCHUNK), 256>>>(A_log);
    scan_phaseB<<<DS/256, 256>>>();
    scan_phaseC<<<dim3(DI/256, NCHUNK), 256>>>(A_log, Dp);

    // 7) out = yo @ W_out + seq  (tensor cores, fused residual + scatter)
    gemm_wmma<1><<<dim3(CDIM/128, LSEQ/128), 256, GEMM_SMEM>>>(
        a2h, a2l, b2h, b2l, nullptr, DI, CDIM, x, y, out);
}

// round 8
// speedup vs baseline: 10.1576x; 1.0127x over previous
#include <cuda_runtime.h>
#include <cuda_bf16.h>
#include <mma.h>
#include <cstdint>

using namespace nvcuda;

#define LSEQ 4608
#define CDIM 640
#define DI   1280
#define DXZ  2560
#define NPROJ 56
#define RANK  40
#define PLANE 2304          // 48*48
#define XFSZ  (640*2304)
#define PSLICE (LSEQ*NPROJ)
#define NCHUNK 72
#define CLEN   64
#define DS     (DI*8)
#define KSPLIT 16

// ---------------- scratch ----------------
__device__ float g_xz  [LSEQ*DXZ];
__device__ float g_xa  [LSEQ*DI];
__device__ float g_proj[LSEQ*NPROJ];
__device__ float g_pp  [KSPLIT*PSLICE];
__device__ float g_dt  [LSEQ*DI];
__device__ float g_cP  [NCHUNK*DS];
__device__ float g_cH  [NCHUNK*DS];
__device__ float g_h0  [NCHUNK*DS];
// bf16 hi/lo operands for tensor-core GEMMs (16B-aligned for cp.async)
__device__ __align__(256) __nv_bfloat16 g_a1hi[LSEQ*CDIM], g_a1lo[LSEQ*CDIM]; // ln(seq)
__device__ __align__(256) __nv_bfloat16 g_b1hi[DXZ*CDIM],  g_b1lo[DXZ*CDIM];  // W_in^T  [2560,640]
__device__ __align__(256) __nv_bfloat16 g_a2hi[LSEQ*DI],   g_a2lo[LSEQ*DI];   // yo
__device__ __align__(256) __nv_bfloat16 g_b2hi[CDIM*DI],   g_b2lo[CDIM*DI];   // W_out^T [640,1280]

// ---------------- helpers ----------------
#define CP_ASYNC16(dst, src) \
    asm volatile("cp.async.cg.shared.global [%0], [%1], 16;" :: "r"(dst), "l"(src) : "memory")
#define CP_COMMIT() asm volatile("cp.async.commit_group;" ::: "memory")
#define CP_WAIT(n)  asm volatile("cp.async.wait_group %0;" :: "n"(n) : "memory")

__device__ __forceinline__ uint32_t smem_u32(const void* p){
    uint32_t a;
    asm("{ .reg .u64 t; cvta.to.shared.u64 t, %1; cvt.u32.u64 %0, t; }" : "=r"(a) : "l"(p));
    return a;
}
__device__ __forceinline__ float silu_f(float v){ return v / (1.0f + __expf(-v)); }
__device__ __forceinline__ void split_store(float v, __nv_bfloat16* hi, __nv_bfloat16* lo, size_t off){
    __nv_bfloat16 h = __float2bfloat16(v);
    hi[off] = h;
    lo[off] = __float2bfloat16(v - __bfloat162float(h));
}

// ---------------- 1) gather + layernorm -> bf16 hi/lo (coalesced via smem transpose) ----
// Block = 24 contiguous w-positions of one (x|y, h) half-row. Grid = 192.
#define LN_SMEM ((16000 + 640 + 640) * 4)
__global__ void __launch_bounds__(256)
ln_kernel(const float* __restrict__ x, const float* __restrict__ yy,
          const float* __restrict__ g, const float* __restrict__ b){
    extern __shared__ float sm[];             // T[640*25] | gg[640] | bb[640]
    float* T  = sm;
    float* gg = sm + 16000;
    float* bb = sm + 16640;
    int bid = blockIdx.x;                     // 0..191
    bool isx = bid < 96;
    int hb = bid - (isx ? 0 : 96);
    int h  = hb >> 1;
    int w0 = (hb & 1) * 24;
    const float* src = (isx ? x : yy) + h*48 + w0;
    int tid = threadIdx.x;

    for (int e = tid; e < 640; e += 256){ gg[e] = g[e]; bb[e] = b[e]; }
    for (int e = tid; e < 15360; e += 256){
        int c = e / 24, w = e - c*24;
        T[c*25 + w] = src[(size_t)c * PLANE + w];
    }
    __syncthreads();

    int wid = tid >> 5, lane = tid & 31;
    #pragma unroll
    for (int pi = 0; pi < 3; pi++){
        int p = wid + pi*8;                   // 0..23
        float s = 0.f, s2 = 0.f;
        #pragma unroll
        for (int k = 0; k < 20; k++){
            float v = T[(lane + k*32)*25 + p];
            s += v; s2 += v*v;
        }
        #pragma unroll
        for (int o = 16; o; o >>= 1){
            s  += __shfl_xor_sync(0xffffffffu, s , o);
            s2 += __shfl_xor_sync(0xffffffffu, s2, o);
        }
        float mean = s  * (1.f/640.f);
        float var  = s2 * (1.f/640.f) - mean*mean;
        float inv  = rsqrtf(var + 1e-5f);
        int l = h*96 + (isx ? 0 : 48) + w0 + p;
        size_t base = (size_t)l * CDIM;
        #pragma unroll
        for (int k = 0; k < 20; k++){
            int c = lane + k*32;
            float o = (T[c*25 + p] - mean) * inv * gg[c] + bb[c];
            split_store(o, g_a1hi, g_a1lo, base + c);
        }
    }
}

// ---------------- weight transpose + bf16 split: W[K,N] -> Wt[n*K+k] ----------------
__global__ void transpose_split(const float* __restrict__ W,
                                __nv_bfloat16* __restrict__ hi, __nv_bfloat16* __restrict__ lo,
                                int K, int N){
    __shared__ float tile[32][33];
    int n0 = blockIdx.x * 32, k0 = blockIdx.y * 32;
    int tx = threadIdx.x, ty = threadIdx.y;   // (32, 8)
    #pragma unroll
    for (int i = 0; i < 4; i++)
        tile[ty + 8*i][tx] = W[(size_t)(k0 + ty + 8*i) * N + n0 + tx];
    __syncthreads();
    #pragma unroll
    for (int i = 0; i < 4; i++){
        float v = tile[tx][ty + 8*i];
        size_t o = (size_t)(n0 + ty + 8*i) * K + k0 + tx;
        __nv_bfloat16 h = __float2bfloat16(v);
        hi[o] = h;
        lo[o] = __float2bfloat16(v - __bfloat162float(h));
    }
}

// ---------------- wmma bf16-split GEMM: C[M,Nc] = A[M,K] @ B[Nc,K]^T ----------------
// 3 terms: Ahi*Bhi + Alo*Bhi + Ahi*Blo, fp32 accumulators.
// MW = warps along M. MW=4: 128xM tile, warp 32x64.  MW=2: 64xM tile, warp 32x32.
#define LDS_E 40                         // bf16 smem row stride (80B)

template<int MODE, int MW>
__global__ void __launch_bounds__(256, 2)
gemm_wmma(const __nv_bfloat16* __restrict__ Ahi, const __nv_bfloat16* __restrict__ Alo,
          const __nv_bfloat16* __restrict__ Bhi, const __nv_bfloat16* __restrict__ Blo,
          float* __restrict__ C, int K, int Nc,
          const float* __restrict__ rx, const float* __restrict__ ry,
          float* __restrict__ outp){
    constexpr int MTILE = MW * 32;
    constexpr int NW    = 8 / MW;
    constexpr int WNT   = 128 / NW;           // warp N-tile: 64 or 32
    constexpr int NJ    = WNT / 16;           // 4 or 2
    constexpr int A_TB  = MTILE * LDS_E * 2;
    constexpr int B_TB  = 128 * LDS_E * 2;
    constexpr int SS    = 2*A_TB + 2*B_TB;    // stage stride
    constexpr int STGL  = WNT + 4;            // fp32 staging ldm (mult of 4)

    extern __shared__ __align__(32) char smem[];
    uint32_t sbase = smem_u32(smem);
    int tid = threadIdx.x;
    int wid = tid >> 5, lane = tid & 31;
    int wr = wid % MW, wc = wid / MW;
    int n0 = blockIdx.x * 128, m0 = blockIdx.y * MTILE;

    const char* asrc[2] = {
        (const char*)(Ahi + (size_t)m0 * K), (const char*)(Alo + (size_t)m0 * K) };
    const char* bsrc[2] = {
        (const char*)(Bhi + (size_t)n0 * K), (const char*)(Blo + (size_t)n0 * K) };
    int rowbytes = K * 2;
    int nstage = K / 32;

    wmma::fragment<wmma::accumulator, 16, 16, 16, float> acc[2][NJ];
    #pragma unroll
    for (int i = 0; i < 2; i++)
        #pragma unroll
        for (int j = 0; j < NJ; j++) wmma::fill_fragment(acc[i][j], 0.f);

    auto load_stage = [&](int st, int k0bytes){
        uint32_t sb = sbase + (uint32_t)(st * SS);
        #pragma unroll
        for (int tl = 0; tl < 2; tl++){
            const char* bp = asrc[tl] + k0bytes;
            uint32_t tb = sb + (uint32_t)(tl * A_TB);
            #pragma unroll
            for (int j = 0; j < (MTILE*4)/256; j++){
                int cidx = tid + j*256;
                int row = cidx >> 2, c = cidx & 3;
                CP_ASYNC16(tb + (uint32_t)(row*(LDS_E*2) + c*16),
                           bp + (size_t)row * rowbytes + c*16);
            }
        }
        #pragma unroll
        for (int tl = 0; tl < 2; tl++){
            const char* bp = bsrc[tl] + k0bytes;
            uint32_t tb = sb + (uint32_t)(2*A_TB + tl * B_TB);
            #pragma unroll
            for (int j = 0; j < 2; j++){
                int cidx = tid + j*256;
                int row = cidx >> 2, c = cidx & 3;
                CP_ASYNC16(tb + (uint32_t)(row*(LDS_E*2) + c*16),
                           bp + (size_t)row * rowbytes + c*16);
            }
        }
        CP_COMMIT();
    };

    load_stage(0, 0);

    for (int t = 0; t < nstage; t++){
        int s = t & 1;
        if (t + 1 < nstage){
            load_stage(s ^ 1, (t+1)*64);
            CP_WAIT(1);
        } else {
            CP_WAIT(0);
        }
        __syncthreads();

        const __nv_bfloat16* As_h = (const __nv_bfloat16*)(smem + s*SS);
        const __nv_bfloat16* As_l = (const __nv_bfloat16*)(smem + s*SS + A_TB);
        const __nv_bfloat16* Bs_h = (const __nv_bfloat16*)(smem + s*SS + 2*A_TB);
        const __nv_bfloat16* Bs_l = (const __nv_bfloat16*)(smem + s*SS + 2*A_TB + B_TB);

        #pragma unroll
        for (int kf = 0; kf < 2; kf++){
            wmma::fragment<wmma::matrix_a, 16, 16, 16, __nv_bfloat16, wmma::row_major> ah[2], al[2];
            #pragma unroll
            for (int i = 0; i < 2; i++){
                int r = wr*32 + i*16;
                wmma::load_matrix_sync(ah[i], As_h + r*LDS_E + kf*16, LDS_E);
                wmma::load_matrix_sync(al[i], As_l + r*LDS_E + kf*16, LDS_E);
            }
            #pragma unroll
            for (int j = 0; j < NJ; j++){
                wmma::fragment<wmma::matrix_b, 16, 16, 16, __nv_bfloat16, wmma::col_major> bh, bl;
                int c = wc*WNT + j*16;
                wmma::load_matrix_sync(bh, Bs_h + c*LDS_E + kf*16, LDS_E);
                wmma::load_matrix_sync(bl, Bs_l + c*LDS_E + kf*16, LDS_E);
                #pragma unroll
                for (int i = 0; i < 2; i++){
                    wmma::mma_sync(acc[i][j], ah[i], bh, acc[i][j]);
                    wmma::mma_sync(acc[i][j], al[i], bh, acc[i][j]);
                    wmma::mma_sync(acc[i][j], ah[i], bl, acc[i][j]);
                }
            }
        }
        __syncthreads();
    }

    if (MODE == 0){
        #pragma unroll
        for (int i = 0; i < 2; i++)
            #pragma unroll
            for (int j = 0; j < NJ; j++){
                float* cp = C + (size_t)(m0 + wr*32 + i*16) * Nc + n0 + wc*WNT + j*16;
                wmma::store_matrix_sync(cp, acc[i][j], Nc, wmma::mem_row_major);
            }
    } else {
        // stage 32xWNT warp tile into padded smem, then coalesced scatter
        float* stg = (float*)smem + (size_t)wid * (32*STGL);
        #pragma unroll
        for (int i = 0; i < 2; i++)
            #pragma unroll
            for (int j = 0; j < NJ; j++)
                wmma::store_matrix_sync(stg + i*16*STGL + j*16, acc[i][j], STGL,
                                        wmma::mem_row_major);
        __syncwarp();

        int row = m0 + wr*32 + lane;          // lane = local row
        int h   = row / 96;
        int w2  = row - h*96;
        bool isx = (w2 < 48);
        int  w   = isx ? w2 : (w2 - 48);
        const float* rsrc = (isx ? rx : ry) + h*48 + w;
        float* od = outp + (isx ? 0 : XFSZ) + h*48 + w;
        #pragma unroll 8
        for (int j = 0; j < WNT; j++){
            int col = n0 + wc*WNT + j;
            od[(size_t)col * PLANE] = stg[lane*STGL + j] + rsrc[(size_t)col * PLANE];
        }
    }
}
#define GEMM_SMEM_MW4 (2 * (2*(128*LDS_E*2) + 2*(128*LDS_E*2)))   // 81920
#define GEMM_SMEM_MW2 (2 * (2*(64*LDS_E*2)  + 2*(128*LDS_E*2)))   // 61440

// ---------------- 3) causal depthwise conv (K=4) + SiLU ----------------
__global__ void conv_silu_kernel(const float* __restrict__ cw){
    int d = blockIdx.x * 256 + threadIdx.x;
    int l = blockIdx.y;
    float4 wv = ((const float4*)cw)[d];
    const float* xp = g_xz + d;
    float acc = wv.w * xp[(size_t)l * DXZ];
    if (l >= 1) acc += wv.z * xp[(size_t)(l-1) * DXZ];
    if (l >= 2) acc += wv.y * xp[(size_t)(l-2) * DXZ];
    if (l >= 3) acc += wv.x * xp[(size_t)(l-3) * DXZ];
    g_xa[(size_t)l * DI + d] = silu_f(acc);
}

// ---------------- 4) proj GEMM split-K=16: xa @ W_xproj ----------------
__global__ void proj_gemm(const float* __restrict__ A, const float* __restrict__ B){
    __shared__ float As[16][64];
    __shared__ float Bs[16][64];
    int tid = threadIdx.x;
    int by  = blockIdx.x;                 // 0..71
    int ks  = blockIdx.y;                 // 0..15
    int k0b = ks * 80;

    int arow = tid >> 2;
    int acol = (tid & 3) * 4;
    const float* Ap = A + (size_t)(by*64 + arow) * DI + k0b + acol;

    float acc[4][4];
    #pragma unroll
    for (int i = 0; i < 4; i++)
        #pragma unroll
        for (int j = 0; j < 4; j++) acc[i][j] = 0.f;

    int ty = tid >> 4, tx = tid & 15;

    for (int k0 = 0; k0 < 80; k0 += 16){
        float4 av = *(const float4*)Ap;
        float bl[4];
        #pragma unroll
        for (int q = 0; q < 4; q++){
            int e = tid*4 + q;
            int rr = e >> 6, c = e & 63;
            bl[q] = (c < NPROJ) ? B[(size_t)(k0b + k0 + rr) * NPROJ + c] : 0.f;
        }
        __syncthreads();
        As[acol+0][arow] = av.x;
        As[acol+1][arow] = av.y;
        As[acol+2][arow] = av.z;
        As[acol+3][arow] = av.w;
        #pragma unroll
        for (int q = 0; q < 4; q++){
            int e = tid*4 + q;
            Bs[e >> 6][e & 63] = bl[q];
        }
        __syncthreads();
        #pragma unroll
        for (int k = 0; k < 16; k++){
            float ar[4], br[4];
            #pragma unroll
            for (int i = 0; i < 4; i++) ar[i] = As[k][ty*4 + i];
            #pragma unroll
            for (int j = 0; j < 4; j++) br[j] = Bs[k][tx*4 + j];
            #pragma unroll
            for (int i = 0; i < 4; i++)
                #pragma unroll
                for (int j = 0; j < 4; j++)
                    acc[i][j] = fmaf(ar[i], br[j], acc[i][j]);
        }
        __syncthreads();
        Ap += 16;
    }
    float* Cp = g_pp + (size_t)ks * PSLICE;
    #pragma unroll
    for (int i = 0; i < 4; i++){
        int row = by*64 + ty*4 + i;
        #pragma unroll
        for (int j = 0; j < 4; j++){
            int col = tx*4 + j;
            if (col < NPROJ) Cp[(size_t)row * NPROJ + col] = acc[i][j];
        }
    }
}

__global__ void proj_reduce(){
    int i = blockIdx.x * 256 + threadIdx.x;
    if (i < PSLICE){
        float a = 0.f;
        #pragma unroll
        for (int k = 0; k < KSPLIT; k++) a += g_pp[(size_t)k * PSLICE + i];
        g_proj[i] = a;
    }
}

// ---------------- 5) dt = softplus(proj[:, :40] @ W_dt + bias), 16 rows/block ------
__global__ void dt_kernel(const float* __restrict__ Wdt, const float* __restrict__ bias){
    __shared__ float pr[16][RANK];
    int t  = threadIdx.x;
    int d  = blockIdx.x * 256 + t;       // grid.x = 5
    int l0 = blockIdx.y * 16;            // grid.y = 288
    for (int e = t; e < 16*RANK; e += 256)
        pr[e / RANK][e % RANK] = g_proj[(size_t)(l0 + e / RANK) * NPROJ + (e % RANK)];
    __syncthreads();

    float acc[16];
    #pragma unroll
    for (int j = 0; j < 16; j++) acc[j] = 0.f;
    for (int k = 0; k < RANK; k++){
        float wv = Wdt[(size_t)k * DI + d];
        #pragma unroll
        for (int j = 0; j < 16; j++) acc[j] = fmaf(pr[j][k], wv, acc[j]);
    }
    float bb = bias[d];
    #pragma unroll
    for (int j = 0; j < 16; j++){
        float v = acc[j] + bb;
        float sp = (v > 20.f) ? v : log1pf(__expf(v));
        g_dt[(size_t)(l0 + j) * DI + d] = sp;
    }
}

// ---------------- 6) chunked parallel scan ----------------
__global__ void __launch_bounds__(256)
scan_phaseA(const float* __restrict__ A_log){
    int t = threadIdx.x;
    int d = blockIdx.x * 256 + t;
    int g = blockIdx.y;

    float Ac[8];
    #pragma unroll
    for (int s = 0; s < 8; s++) Ac[s] = -__expf(A_log[d*8 + s]);
    bool fast = true;
    #pragma unroll
    for (int s = 0; s < 8; s++){
        float r = Ac[s] / Ac[0];
        if (fabsf(r - (float)(s+1)) > 1e-3f) fast = false;
    }

    float h[8];
    #pragma unroll
    for (int s = 0; s < 8; s++) h[s] = 0.f;
    float Etot = 1.f;

    const float* dtp = g_dt   + (size_t)(g*CLEN) * DI + d;
    const float* xap = g_xa   + (size_t)(g*CLEN) * DI + d;
    const float* bp  = g_proj + (size_t)(g*CLEN) * NPROJ + RANK;

    if (fast){
        for (int l = 0; l < CLEN; l++){
            float dtv = *dtp, xav = *xap;
            float e1 = __expf(dtv * Ac[0]);
            float db = dtv * xav;
            Etot *= e1;
            float p = 1.f;
            #pragma unroll
            for (int s = 0; s < 8; s++){
                p *= e1;
                h[s] = fmaf(p, h[s], db * __ldg(bp + s));
            }
            dtp += DI; xap += DI; bp += NPROJ;
        }
        size_t base = (size_t)g * DS + d*8;
        float P = 1.f;
        #pragma unroll
        for (int s = 0; s < 8; s++){
            P *= Etot;
            g_cP[base + s] = P;
            g_cH[base + s] = h[s];
        }
    } else {
        float Ps[8];
        #pragma unroll
        for (int s = 0; s < 8; s++) Ps[s] = 1.f;
        for (int l = 0; l < CLEN; l++){
            float dtv = *dtp, xav = *xap;
            float db = dtv * xav;
            #pragma unroll
            for (int s = 0; s < 8; s++){
                float dA = __expf(dtv * Ac[s]);
                Ps[s] *= dA;
                h[s] = fmaf(dA, h[s], db * __ldg(bp + s));
            }
            dtp += DI; xap += DI; bp += NPROJ;
        }
        size_t base = (size_t)g * DS + d*8;
        #pragma unroll
        for (int s = 0; s < 8; s++){
            g_cP[base + s] = Ps[s];
            g_cH[base + s] = h[s];
        }
    }
}

__global__ void scan_phaseB(){
    int idx = blockIdx.x * 256 + threadIdx.x;
    float h = 0.f;
    for (int g = 0; g < NCHUNK; g++){
        size_t o = (size_t)g * DS + idx;
        g_h0[o] = h;
        h = fmaf(g_cP[o], h, g_cH[o]);
    }
}

__global__ void __launch_bounds__(256)
scan_phaseC(const float* __restrict__ A_log, const float* __restrict__ Dp){
    int t = threadIdx.x;
    int d = blockIdx.x * 256 + t;
    int g = blockIdx.y;

    float Ac[8];
    #pragma unroll
    for (int s = 0; s < 8; s++) Ac[s] = -__expf(A_log[d*8 + s]);
    bool fast = true;
    #pragma unroll
    for (int s = 0; s < 8; s++){
        float r = Ac[s] / Ac[0];
        if (fabsf(r - (float)(s+1)) > 1e-3f) fast = false;
    }

    float h[8];
    size_t hb = (size_t)g * DS + d*8;
    #pragma unroll
    for (int s = 0; s < 8; s++) h[s] = g_h0[hb + s];
    float Dval = Dp[d];

    const float* dtp = g_dt   + (size_t)(g*CLEN) * DI + d;
    const float* xap = g_xa   + (size_t)(g*CLEN) * DI + d;
    const float* zp  = g_xz   + (size_t)(g*CLEN) * DXZ + DI + d;
    const float* bp  = g_proj + (size_t)(g*CLEN) * NPROJ + RANK;
    size_t yoff = (size_t)(g*CLEN) * DI + d;

    if (fast){
        for (int l = 0; l < CLEN; l++){
            float dtv = *dtp, xav = *xap;
            float e1 = __expf(dtv * Ac[0]);
            float db = dtv * xav;
            float p = 1.f, yv = 0.f;
            #pragma unroll
            for (int s = 0; s < 8; s++){
                p *= e1;
                h[s] = fmaf(p, h[s], db * __ldg(bp + s));
                yv = fmaf(h[s], __ldg(bp + 8 + s), yv);
            }
            float val = (yv + xav * Dval) * silu_f(*zp);
            split_store(val, g_a2hi, g_a2lo, yoff);
            dtp += DI; xap += DI; zp += DXZ; bp += NPROJ; yoff += DI;
        }
    } else {
        for (int l = 0; l < CLEN; l++){
            float dtv = *dtp, xav = *xap;
            float db = dtv * xav;
            float yv = 0.f;
            #pragma unroll
            for (int s = 0; s < 8; s++){
                float dA = __expf(dtv * Ac[s]);
                h[s] = fmaf(dA, h[s], db * __ldg(bp + s));
                yv = fmaf(h[s], __ldg(bp + 8 + s), yv);
            }
            float val = (yv + xav * Dval) * silu_f(*zp);
            split_store(val, g_a2hi, g_a2lo, yoff);
            dtp += DI; xap += DI; zp += DXZ; bp += NPROJ; yoff += DI;
        }
    }
}

// ---------------- launch ----------------
extern "C" void kernel_launch(void* const* d_in, const int* in_sizes, int n_in,
                              void* d_out, int out_size){
    const float* x       = (const float*)d_in[0];
    const float* y       = (const float*)d_in[1];
    const float* ln_g    = (const float*)d_in[2];
    const float* ln_b    = (const float*)d_in[3];
    const float* W_in    = (const float*)d_in[4];
    const float* conv_w  = (const float*)d_in[5];
    const float* W_xproj = (const float*)d_in[6];
    const float* W_dt    = (const float*)d_in[7];
    const float* dt_bias = (const float*)d_in[8];
    const float* A_log   = (const float*)d_in[9];
    const float* Dp      = (const float*)d_in[10];
    const float* W_out   = (const float*)d_in[11];
    float* out = (float*)d_out;

    cudaFuncSetAttribute(gemm_wmma<0,4>, cudaFuncAttributeMaxDynamicSharedMemorySize, GEMM_SMEM_MW4);
    cudaFuncSetAttribute(gemm_wmma<1,2>, cudaFuncAttributeMaxDynamicSharedMemorySize, GEMM_SMEM_MW2);
    cudaFuncSetAttribute(ln_kernel, cudaFuncAttributeMaxDynamicSharedMemorySize, LN_SMEM);

    float *xz_p, *xa_p;
    __nv_bfloat16 *a1h, *a1l, *b1h, *b1l, *a2h, *a2l, *b2h, *b2l;
    cudaGetSymbolAddress((void**)&xz_p, g_xz);
    cudaGetSymbolAddress((void**)&xa_p, g_xa);
    cudaGetSymbolAddress((void**)&a1h, g_a1hi);  cudaGetSymbolAddress((void**)&a1l, g_a1lo);
    cudaGetSymbolAddress((void**)&b1h, g_b1hi);  cudaGetSymbolAddress((void**)&b1l, g_b1lo);
    cudaGetSymbolAddress((void**)&a2h, g_a2hi);  cudaGetSymbolAddress((void**)&a2l, g_a2lo);
    cudaGetSymbolAddress((void**)&b2h, g_b2hi);  cudaGetSymbolAddress((void**)&b2l, g_b2lo);

    // weight transposes + bf16 split
    transpose_split<<<dim3(DXZ/32, CDIM/32), dim3(32,8)>>>(W_in,  b1h, b1l, CDIM, DXZ);
    transpose_split<<<dim3(CDIM/32, DI/32),  dim3(32,8)>>>(W_out, b2h, b2l, DI,   CDIM);

    // 1) gather + layernorm -> a1 (bf16 hi/lo)
    ln_kernel<<<192, 256, LN_SMEM>>>(x, y, ln_g, ln_b);

    // 2) xz = ln(seq) @ W_in   (128x128 tiles, grid 720)
    gemm_wmma<0,4><<<dim3(DXZ/128, LSEQ/128), 256, GEMM_SMEM_MW4>>>(
        a1h, a1l, b1h, b1l, xz_p, CDIM, DXZ, nullptr, nullptr, nullptr);

    // 3) xa = silu(causal_dwconv(xp))
    conv_silu_kernel<<<dim3(DI/256, LSEQ), 256>>>(conv_w);

    // 4) proj = xa @ W_xproj (split-K=16)
    proj_gemm<<<dim3(LSEQ/64, KSPLIT), 256>>>(xa_p, W_xproj);
    proj_reduce<<<(PSLICE + 255)/256, 256>>>();

    // 5) dt (16 rows/block)
    dt_kernel<<<dim3(DI/256, LSEQ/16), 256>>>(W_dt, dt_bias);

    // 6) chunked parallel scan + gating -> a2 (bf16 hi/lo)
    scan_phaseA<<<dim3(DI/256, NCHUNK), 256>>>(A_log);
    scan_phaseB<<<DS/256, 256>>>();
    scan_phaseC<<<dim3(DI/256, NCHUNK), 256>>>(A_log, Dp);

    // 7) out = yo @ W_out + seq  (64x128 tiles, grid 360, fused residual + scatter)
    gemm_wmma<1,2><<<dim3(CDIM/128, LSEQ/64), 256, GEMM_SMEM_MW2>>>(
        a2h, a2l, b2h, b2l, nullptr, DI, CDIM, x, y, out);
}